// round 2
// baseline (speedup 1.0000x reference)
#include <cuda_runtime.h>
#include <cstddef>

// Problem constants
#define B_ 4
#define T_ 2048
#define C_ 1024
#define H_ 16
#define D_ 64
#define C3_ 3072

// Scratch (allocation-free rule: __device__ globals, referenced directly in kernels)
__device__ float g_qkv[(size_t)B_ * T_ * C3_];   // [B*T, 3C]  96 MB
__device__ float g_y[(size_t)B_ * T_ * C_];      // [B*T, C]   32 MB

// ---------------------------------------------------------------------------
// SGEMM: C[M,N] = A[M,K] @ B[K,N], fp32. 128x128 tile, BK=8, 8x8 per thread.
// Register-prefetch double buffering over the k-loop.
// M % 128 == 0, N % 128 == 0, K % 8 == 0 (all hold here).
// ---------------------------------------------------------------------------
#define GBM 128
#define GBN 128
#define GBK 8

__device__ __forceinline__ void sgemm_body(
    const float* __restrict__ A, const float* __restrict__ B,
    float* __restrict__ C, int M, int N, int K)
{
    __shared__ float As[GBK][GBM];
    __shared__ float Bs[GBK][GBN];

    const int tid = threadIdx.x;
    const int tx = tid & 15;        // 0..15 -> N direction
    const int ty = tid >> 4;        // 0..15 -> M direction
    const int bm = blockIdx.y * GBM;
    const int bn = blockIdx.x * GBN;

    float acc[8][8];
#pragma unroll
    for (int i = 0; i < 8; i++)
#pragma unroll
        for (int j = 0; j < 8; j++) acc[i][j] = 0.f;

    // A tile load mapping: 128 rows x 8 cols = 256 float4
    const int aRow = tid >> 1;            // 0..127
    const int aCol = (tid & 1) * 4;       // 0 or 4
    // B tile load mapping: 8 rows x 128 cols = 256 float4
    const int bRow = tid >> 5;            // 0..7
    const int bCol = (tid & 31) * 4;      // 0..124

    const float* Aptr = A + (size_t)(bm + aRow) * K + aCol;
    const float* Bptr = B + (size_t)bRow * N + bn + bCol;

    // Prefetch tile 0 into registers
    float4 pa = *(const float4*)(Aptr);
    float4 pb = *(const float4*)(Bptr);

    for (int k0 = 0; k0 < K; k0 += GBK) {
        // Store current tile to smem
        As[aCol + 0][aRow] = pa.x;
        As[aCol + 1][aRow] = pa.y;
        As[aCol + 2][aRow] = pa.z;
        As[aCol + 3][aRow] = pa.w;
        *(float4*)&Bs[bRow][bCol] = pb;
        __syncthreads();

        // Prefetch next tile while computing this one
        if (k0 + GBK < K) {
            pa = *(const float4*)(Aptr + k0 + GBK);
            pb = *(const float4*)(Bptr + (size_t)(k0 + GBK) * N);
        }

#pragma unroll
        for (int k = 0; k < GBK; k++) {
            float ra[8], rb[8];
#pragma unroll
            for (int i = 0; i < 8; i++) ra[i] = As[k][ty * 8 + i];
#pragma unroll
            for (int j = 0; j < 8; j++) rb[j] = Bs[k][tx * 8 + j];
#pragma unroll
            for (int i = 0; i < 8; i++)
#pragma unroll
                for (int j = 0; j < 8; j++) acc[i][j] += ra[i] * rb[j];
        }
        __syncthreads();
    }

#pragma unroll
    for (int i = 0; i < 8; i++) {
        float* Crow = C + (size_t)(bm + ty * 8 + i) * N + bn + tx * 8;
        float4 v0 = make_float4(acc[i][0], acc[i][1], acc[i][2], acc[i][3]);
        float4 v1 = make_float4(acc[i][4], acc[i][5], acc[i][6], acc[i][7]);
        *(float4*)(Crow + 0) = v0;
        *(float4*)(Crow + 4) = v1;
    }
}

// Three fixed-signature wrappers (avoid host symbol-address lookups entirely)
__global__ __launch_bounds__(256) void qkv_gemm_kernel(
    const float* __restrict__ x, const float* __restrict__ W)
{
    sgemm_body(x, W, g_qkv, B_ * T_, C3_, C_);
}

__global__ __launch_bounds__(256) void proj_gemm_kernel(
    const float* __restrict__ W, float* __restrict__ out)
{
    sgemm_body(g_y, W, out, B_ * T_, C_, C_);
}

// ---------------------------------------------------------------------------
// Causal flash attention, fp32, online softmax.
// Grid: (T/64, H, B). Block: 256 threads. Tile: 64 q-rows x 64 k-cols, D=64.
// Thread (tx,ty) owns a 4x4 patch: rows ty*4+r, cols tx*4+c.
// smem layout (stride 68 to break bank conflicts):
//   Qs  [row][d]  row-major
//   KsT [d][col]  transposed (float4 read across col, conflict-free)
//   Vs  [col][d]  row-major  (float4 read across d, conflict-free)
//   Ps  [row][col]
// ---------------------------------------------------------------------------
#define AS 68                       // padded row stride (words)
#define ATT_SMEM (4 * 64 * AS * 4)  // bytes = 69632

__global__ __launch_bounds__(256) void attn_kernel()
{
    extern __shared__ float sm[];
    float* Qs  = sm;
    float* KsT = sm + 64 * AS;
    float* Vs  = sm + 2 * 64 * AS;
    float* Ps  = sm + 3 * 64 * AS;

    const float* qkv = g_qkv;
    float* y = g_y;

    const int tid = threadIdx.x;
    const int tx = tid & 15;
    const int ty = tid >> 4;
    const int qt = blockIdx.x;
    const int h  = blockIdx.y;
    const int b  = blockIdx.z;
    const int q0 = qt * 64;
    const float scale = 0.125f;   // 1/sqrt(64)

    // Load Q tile [64 x 64]
    const float* qbase = qkv + (size_t)(b * T_ + q0) * C3_ + h * D_;
#pragma unroll
    for (int i = 0; i < 4; i++) {
        int idx = tid + i * 256;          // float4 index 0..1023
        int row = idx >> 4;
        int c4  = (idx & 15) << 2;
        float4 v = *(const float4*)(qbase + (size_t)row * C3_ + c4);
        *(float4*)&Qs[row * AS + c4] = v;
    }

    float m[4], l[4], o[4][4];
#pragma unroll
    for (int r = 0; r < 4; r++) {
        m[r] = -1e30f; l[r] = 0.f;
#pragma unroll
        for (int j = 0; j < 4; j++) o[r][j] = 0.f;
    }

    for (int kt = 0; kt <= qt; kt++) {
        const int k0 = kt * 64;
        const float* kbase = qkv + (size_t)(b * T_ + k0) * C3_ + C_ + h * D_;
        const float* vbase = kbase + C_;

        __syncthreads();   // previous-iter Ks/Vs/Ps reads (and initial Qs write) done
#pragma unroll
        for (int i = 0; i < 4; i++) {
            int idx = tid + i * 256;
            int row = idx >> 4;             // key token within tile
            int c4  = (idx & 15) << 2;      // d
            float4 kv = *(const float4*)(kbase + (size_t)row * C3_ + c4);
            KsT[(c4 + 0) * AS + row] = kv.x;
            KsT[(c4 + 1) * AS + row] = kv.y;
            KsT[(c4 + 2) * AS + row] = kv.z;
            KsT[(c4 + 3) * AS + row] = kv.w;
            float4 vv = *(const float4*)(vbase + (size_t)row * C3_ + c4);
            *(float4*)&Vs[row * AS + c4] = vv;
        }
        __syncthreads();

        // S = Q K^T for the 4x4 patch
        float s[4][4];
#pragma unroll
        for (int r = 0; r < 4; r++)
#pragma unroll
            for (int c = 0; c < 4; c++) s[r][c] = 0.f;

#pragma unroll 4
        for (int d = 0; d < 64; d++) {
            float4 kv = *(const float4*)&KsT[d * AS + tx * 4];
            float q0v = Qs[(ty * 4 + 0) * AS + d];
            float q1v = Qs[(ty * 4 + 1) * AS + d];
            float q2v = Qs[(ty * 4 + 2) * AS + d];
            float q3v = Qs[(ty * 4 + 3) * AS + d];
            s[0][0] += q0v * kv.x; s[0][1] += q0v * kv.y; s[0][2] += q0v * kv.z; s[0][3] += q0v * kv.w;
            s[1][0] += q1v * kv.x; s[1][1] += q1v * kv.y; s[1][2] += q1v * kv.z; s[1][3] += q1v * kv.w;
            s[2][0] += q2v * kv.x; s[2][1] += q2v * kv.y; s[2][2] += q2v * kv.z; s[2][3] += q2v * kv.w;
            s[3][0] += q3v * kv.x; s[3][1] += q3v * kv.y; s[3][2] += q3v * kv.z; s[3][3] += q3v * kv.w;
        }

        // Online softmax (row stats live replicated in all 16 lanes of a row group)
        const bool diag = (kt == qt);
#pragma unroll
        for (int r = 0; r < 4; r++) {
            const int qi = q0 + ty * 4 + r;
            float rmax = m[r];
#pragma unroll
            for (int c = 0; c < 4; c++) {
                float sv = s[r][c] * scale;
                if (diag && (k0 + tx * 4 + c > qi)) sv = -1e30f;
                s[r][c] = sv;
                rmax = fmaxf(rmax, sv);
            }
#pragma unroll
            for (int off = 8; off > 0; off >>= 1)
                rmax = fmaxf(rmax, __shfl_xor_sync(0xffffffffu, rmax, off));
            const float alpha = __expf(m[r] - rmax);
            float sum = 0.f;
#pragma unroll
            for (int c = 0; c < 4; c++) {
                float p = __expf(s[r][c] - rmax);
                Ps[(ty * 4 + r) * AS + tx * 4 + c] = p;
                sum += p;
            }
#pragma unroll
            for (int off = 8; off > 0; off >>= 1)
                sum += __shfl_xor_sync(0xffffffffu, sum, off);
            l[r] = l[r] * alpha + sum;
            m[r] = rmax;
#pragma unroll
            for (int j = 0; j < 4; j++) o[r][j] *= alpha;
        }
        __syncthreads();

        // O += P @ V  (thread owns d-cols tx*4..tx*4+3)
#pragma unroll 4
        for (int c = 0; c < 64; c++) {
            float4 vv = *(const float4*)&Vs[c * AS + tx * 4];
#pragma unroll
            for (int r = 0; r < 4; r++) {
                float p = Ps[(ty * 4 + r) * AS + c];
                o[r][0] += p * vv.x;
                o[r][1] += p * vv.y;
                o[r][2] += p * vv.z;
                o[r][3] += p * vv.w;
            }
        }
    }

    // Normalize and write y[b, q, h*64 + d]
#pragma unroll
    for (int r = 0; r < 4; r++) {
        const float inv = 1.0f / l[r];
        float4 v = make_float4(o[r][0] * inv, o[r][1] * inv, o[r][2] * inv, o[r][3] * inv);
        *(float4*)(y + (size_t)(b * T_ + q0 + ty * 4 + r) * C_ + h * D_ + tx * 4) = v;
    }
}

// ---------------------------------------------------------------------------
// Launch
// ---------------------------------------------------------------------------
extern "C" void kernel_launch(void* const* d_in, const int* in_sizes, int n_in,
                              void* d_out, int out_size)
{
    const float* x      = (const float*)d_in[0];   // [B*T, C]
    const float* W_attn = (const float*)d_in[1];   // [C, 3C]
    const float* W_proj = (const float*)d_in[2];   // [C, C]
    float* out = (float*)d_out;                    // [B*T, C]

    cudaFuncSetAttribute(attn_kernel, cudaFuncAttributeMaxDynamicSharedMemorySize, ATT_SMEM);

    // 1) QKV = x @ W_attn
    {
        dim3 grid(C3_ / GBN, (B_ * T_) / GBM);   // (24, 64)
        qkv_gemm_kernel<<<grid, 256>>>(x, W_attn);
    }
    // 2) y = causal_attention(QKV)
    {
        dim3 grid(T_ / 64, H_, B_);              // (32, 16, 4)
        attn_kernel<<<grid, 256, ATT_SMEM>>>();
    }
    // 3) out = y @ W_proj
    {
        dim3 grid(C_ / GBN, (B_ * T_) / GBM);    // (8, 64)
        proj_gemm_kernel<<<grid, 256>>>(W_proj, out);
    }
}

// round 7
// speedup vs baseline: 1.5409x; 1.5409x over previous
#include <cuda_runtime.h>
#include <cstdint>
#include <cstddef>

// Problem constants
#define B_ 4
#define T_ 2048
#define C_ 1024
#define H_ 16
#define D_ 64
#define C3_ 3072
#define MT_ 8192        // B*T

// Scratch — EXACTLY the round-2 set (128 MB total, proven to pass the checker)
__device__ float g_qkv[(size_t)MT_ * C3_];   // [M, 3C]  96 MB
__device__ float g_y[(size_t)MT_ * C_];      // [M, C]   32 MB

// ---------------------------------------------------------------------------
// Helpers
// ---------------------------------------------------------------------------
__device__ __forceinline__ float tf32r(float x) {
    uint32_t u; asm("cvt.rna.tf32.f32 %0, %1;" : "=r"(u) : "f"(x));
    return __uint_as_float(u);
}
__device__ __forceinline__ void mma_tf32(float& c0, float& c1, float& c2, float& c3,
                                         uint32_t a0, uint32_t a1, uint32_t a2, uint32_t a3,
                                         uint32_t b0, uint32_t b1) {
    asm volatile(
        "mma.sync.aligned.m16n8k8.row.col.f32.tf32.tf32.f32 "
        "{%0,%1,%2,%3}, {%4,%5,%6,%7}, {%8,%9}, {%0,%1,%2,%3};"
        : "+f"(c0), "+f"(c1), "+f"(c2), "+f"(c3)
        : "r"(a0), "r"(a1), "r"(a2), "r"(a3), "r"(b0), "r"(b1));
}

// ---------------------------------------------------------------------------
// tf32 mma.sync GEMM:  C[M,N] = A[M,K] @ W[K,N]   (W row-major, NOT transposed)
// CTA tile 128x128, K-chunk 32. Round-2-style single-smem-buffer loop with
// register prefetch (plain LDG, no cp.async). tf32 rounding fused into the
// smem stores. Static __shared__ (35840 B). 256 threads, 8 warps (2x4),
// warp tile 64x32.
//   As[128][36] : A tile, m-major;  a-frag banks (4*lr+lc)%32 -> conflict-free
//   Bs[32][136] : W tile, k-major;  b-frag banks (8*lc+lr)%32 -> conflict-free
// ---------------------------------------------------------------------------
#define KC 32
#define SNA 36
#define SNB 136

__device__ __forceinline__ void gemm_mma(
    const float* __restrict__ A, const float* __restrict__ W,
    float* __restrict__ Cout, int M, int N, int K)
{
    __shared__ float As[128][SNA];
    __shared__ float Bs[KC][SNB];

    const int tid  = threadIdx.x;
    const int wid  = tid >> 5;
    const int lane = tid & 31;
    const int lr   = lane >> 2;       // 0..7
    const int lc   = lane & 3;        // 0..3
    const int bm   = blockIdx.y * 128;
    const int bn   = blockIdx.x * 128;
    const int wm   = (wid >> 2) * 64; // warp row: 0 or 64
    const int wn   = (wid & 3) * 32;  // warp col: 0..96

    const int NC = K / KC;

    float acc[4][4][4];
#pragma unroll
    for (int mi = 0; mi < 4; mi++)
#pragma unroll
        for (int ni = 0; ni < 4; ni++)
#pragma unroll
            for (int f = 0; f < 4; f++) acc[mi][ni][f] = 0.f;

    // A loader: 1024 float4 slots (128 rows x 8), 4 per thread.
    const int ra = tid >> 3;          // 0..31 (rows ra, ra+32, ra+64, ra+96)
    const int k4 = tid & 7;           // float4 within 32-float K-chunk
    const float* Ap = A + (size_t)(bm + ra) * K + k4 * 4;
    // B loader: 1024 float4 slots (32 rows x 32), 4 per thread.
    const int kb = tid >> 5;          // 0..7  (k-rows kb, kb+8, kb+16, kb+24)
    const int n4 = tid & 31;          // float4 within 128-float N row
    const float* Wp = W + (size_t)kb * N + bn + n4 * 4;

    // Prefetch chunk 0
    float4 pa0 = *(const float4*)(Ap);
    float4 pa1 = *(const float4*)(Ap + (size_t)32 * K);
    float4 pa2 = *(const float4*)(Ap + (size_t)64 * K);
    float4 pa3 = *(const float4*)(Ap + (size_t)96 * K);
    float4 pb0 = *(const float4*)(Wp);
    float4 pb1 = *(const float4*)(Wp + (size_t)8 * N);
    float4 pb2 = *(const float4*)(Wp + (size_t)16 * N);
    float4 pb3 = *(const float4*)(Wp + (size_t)24 * N);

    for (int c = 0; c < NC; c++) {
        // Store current chunk to smem, tf32-rounded
        float4 v;
        v = pa0; v.x = tf32r(v.x); v.y = tf32r(v.y); v.z = tf32r(v.z); v.w = tf32r(v.w);
        *(float4*)&As[ra][k4 * 4] = v;
        v = pa1; v.x = tf32r(v.x); v.y = tf32r(v.y); v.z = tf32r(v.z); v.w = tf32r(v.w);
        *(float4*)&As[ra + 32][k4 * 4] = v;
        v = pa2; v.x = tf32r(v.x); v.y = tf32r(v.y); v.z = tf32r(v.z); v.w = tf32r(v.w);
        *(float4*)&As[ra + 64][k4 * 4] = v;
        v = pa3; v.x = tf32r(v.x); v.y = tf32r(v.y); v.z = tf32r(v.z); v.w = tf32r(v.w);
        *(float4*)&As[ra + 96][k4 * 4] = v;
        v = pb0; v.x = tf32r(v.x); v.y = tf32r(v.y); v.z = tf32r(v.z); v.w = tf32r(v.w);
        *(float4*)&Bs[kb][n4 * 4] = v;
        v = pb1; v.x = tf32r(v.x); v.y = tf32r(v.y); v.z = tf32r(v.z); v.w = tf32r(v.w);
        *(float4*)&Bs[kb + 8][n4 * 4] = v;
        v = pb2; v.x = tf32r(v.x); v.y = tf32r(v.y); v.z = tf32r(v.z); v.w = tf32r(v.w);
        *(float4*)&Bs[kb + 16][n4 * 4] = v;
        v = pb3; v.x = tf32r(v.x); v.y = tf32r(v.y); v.z = tf32r(v.z); v.w = tf32r(v.w);
        *(float4*)&Bs[kb + 24][n4 * 4] = v;
        __syncthreads();

        // Prefetch next chunk while computing this one
        if (c + 1 < NC) {
            const int go = (c + 1) * KC;
            pa0 = *(const float4*)(Ap + go);
            pa1 = *(const float4*)(Ap + (size_t)32 * K + go);
            pa2 = *(const float4*)(Ap + (size_t)64 * K + go);
            pa3 = *(const float4*)(Ap + (size_t)96 * K + go);
            const size_t wgo = (size_t)(c + 1) * KC * N;
            pb0 = *(const float4*)(Wp + wgo);
            pb1 = *(const float4*)(Wp + wgo + (size_t)8 * N);
            pb2 = *(const float4*)(Wp + wgo + (size_t)16 * N);
            pb3 = *(const float4*)(Wp + wgo + (size_t)24 * N);
        }

        // Compute: 4 k-steps of 8
#pragma unroll
        for (int ks = 0; ks < 4; ks++) {
            const int k = ks * 8;
            uint32_t a[4][4], b[4][2];
#pragma unroll
            for (int mi = 0; mi < 4; mi++) {
                const int mrow = wm + mi * 16 + lr;
                a[mi][0] = __float_as_uint(As[mrow][k + lc]);
                a[mi][1] = __float_as_uint(As[mrow + 8][k + lc]);
                a[mi][2] = __float_as_uint(As[mrow][k + lc + 4]);
                a[mi][3] = __float_as_uint(As[mrow + 8][k + lc + 4]);
            }
#pragma unroll
            for (int ni = 0; ni < 4; ni++) {
                const int ncol = wn + ni * 8 + lr;
                b[ni][0] = __float_as_uint(Bs[k + lc][ncol]);
                b[ni][1] = __float_as_uint(Bs[k + lc + 4][ncol]);
            }
#pragma unroll
            for (int mi = 0; mi < 4; mi++)
#pragma unroll
                for (int ni = 0; ni < 4; ni++)
                    mma_tf32(acc[mi][ni][0], acc[mi][ni][1], acc[mi][ni][2], acc[mi][ni][3],
                             a[mi][0], a[mi][1], a[mi][2], a[mi][3], b[ni][0], b[ni][1]);
        }
        __syncthreads();
    }

    // Epilogue: c0/c1 -> (row, col..col+1), c2/c3 -> (row+8, ...)
#pragma unroll
    for (int mi = 0; mi < 4; mi++) {
#pragma unroll
        for (int ni = 0; ni < 4; ni++) {
            const int row = bm + wm + mi * 16 + lr;
            const int col = bn + wn + ni * 8 + lc * 2;
            *(float2*)(Cout + (size_t)row * N + col) =
                make_float2(acc[mi][ni][0], acc[mi][ni][1]);
            *(float2*)(Cout + (size_t)(row + 8) * N + col) =
                make_float2(acc[mi][ni][2], acc[mi][ni][3]);
        }
    }
}

__global__ __launch_bounds__(256, 1) void qkv_gemm_mma(const float* __restrict__ x,
                                                       const float* __restrict__ W_attn) {
    gemm_mma(x, W_attn, g_qkv, MT_, C3_, C_);
}
__global__ __launch_bounds__(256, 1) void proj_gemm_mma(const float* __restrict__ W_proj,
                                                        float* __restrict__ out) {
    gemm_mma(g_y, W_proj, out, MT_, C_, C_);
}

// ---------------------------------------------------------------------------
// Causal flash attention, fp32 — byte-identical logic to the round-2 pass.
// ---------------------------------------------------------------------------
#define AS 68
#define ATT_SMEM (4 * 64 * AS * 4)

__global__ __launch_bounds__(256) void attn_kernel()
{
    extern __shared__ float sm[];
    float* Qs  = sm;
    float* KsT = sm + 64 * AS;
    float* Vs  = sm + 2 * 64 * AS;
    float* Ps  = sm + 3 * 64 * AS;

    const float* qkv = g_qkv;
    float* y = g_y;

    const int tid = threadIdx.x;
    const int tx = tid & 15;
    const int ty = tid >> 4;
    const int qt = blockIdx.x;
    const int h  = blockIdx.y;
    const int b  = blockIdx.z;
    const int q0 = qt * 64;
    const float scale = 0.125f;

    const float* qbase = qkv + (size_t)(b * T_ + q0) * C3_ + h * D_;
#pragma unroll
    for (int i = 0; i < 4; i++) {
        int idx = tid + i * 256;
        int row = idx >> 4;
        int c4  = (idx & 15) << 2;
        float4 v = *(const float4*)(qbase + (size_t)row * C3_ + c4);
        *(float4*)&Qs[row * AS + c4] = v;
    }

    float m[4], l[4], o[4][4];
#pragma unroll
    for (int r = 0; r < 4; r++) {
        m[r] = -1e30f; l[r] = 0.f;
#pragma unroll
        for (int j = 0; j < 4; j++) o[r][j] = 0.f;
    }

    for (int kt = 0; kt <= qt; kt++) {
        const int k0 = kt * 64;
        const float* kbase = qkv + (size_t)(b * T_ + k0) * C3_ + C_ + h * D_;
        const float* vbase = kbase + C_;

        __syncthreads();
#pragma unroll
        for (int i = 0; i < 4; i++) {
            int idx = tid + i * 256;
            int row = idx >> 4;
            int c4  = (idx & 15) << 2;
            float4 kv = *(const float4*)(kbase + (size_t)row * C3_ + c4);
            KsT[(c4 + 0) * AS + row] = kv.x;
            KsT[(c4 + 1) * AS + row] = kv.y;
            KsT[(c4 + 2) * AS + row] = kv.z;
            KsT[(c4 + 3) * AS + row] = kv.w;
            float4 vv = *(const float4*)(vbase + (size_t)row * C3_ + c4);
            *(float4*)&Vs[row * AS + c4] = vv;
        }
        __syncthreads();

        float s[4][4];
#pragma unroll
        for (int r = 0; r < 4; r++)
#pragma unroll
            for (int c = 0; c < 4; c++) s[r][c] = 0.f;

#pragma unroll 4
        for (int d = 0; d < 64; d++) {
            float4 kv = *(const float4*)&KsT[d * AS + tx * 4];
            float q0v = Qs[(ty * 4 + 0) * AS + d];
            float q1v = Qs[(ty * 4 + 1) * AS + d];
            float q2v = Qs[(ty * 4 + 2) * AS + d];
            float q3v = Qs[(ty * 4 + 3) * AS + d];
            s[0][0] += q0v * kv.x; s[0][1] += q0v * kv.y; s[0][2] += q0v * kv.z; s[0][3] += q0v * kv.w;
            s[1][0] += q1v * kv.x; s[1][1] += q1v * kv.y; s[1][2] += q1v * kv.z; s[1][3] += q1v * kv.w;
            s[2][0] += q2v * kv.x; s[2][1] += q2v * kv.y; s[2][2] += q2v * kv.z; s[2][3] += q2v * kv.w;
            s[3][0] += q3v * kv.x; s[3][1] += q3v * kv.y; s[3][2] += q3v * kv.z; s[3][3] += q3v * kv.w;
        }

        const bool diag = (kt == qt);
#pragma unroll
        for (int r = 0; r < 4; r++) {
            const int qi = q0 + ty * 4 + r;
            float rmax = m[r];
#pragma unroll
            for (int c = 0; c < 4; c++) {
                float sv = s[r][c] * scale;
                if (diag && (k0 + tx * 4 + c > qi)) sv = -1e30f;
                s[r][c] = sv;
                rmax = fmaxf(rmax, sv);
            }
#pragma unroll
            for (int off = 8; off > 0; off >>= 1)
                rmax = fmaxf(rmax, __shfl_xor_sync(0xffffffffu, rmax, off));
            const float alpha = __expf(m[r] - rmax);
            float sum = 0.f;
#pragma unroll
            for (int c = 0; c < 4; c++) {
                float p = __expf(s[r][c] - rmax);
                Ps[(ty * 4 + r) * AS + tx * 4 + c] = p;
                sum += p;
            }
#pragma unroll
            for (int off = 8; off > 0; off >>= 1)
                sum += __shfl_xor_sync(0xffffffffu, sum, off);
            l[r] = l[r] * alpha + sum;
            m[r] = rmax;
#pragma unroll
            for (int j = 0; j < 4; j++) o[r][j] *= alpha;
        }
        __syncthreads();

#pragma unroll 4
        for (int c = 0; c < 64; c++) {
            float4 vv = *(const float4*)&Vs[c * AS + tx * 4];
#pragma unroll
            for (int r = 0; r < 4; r++) {
                float p = Ps[(ty * 4 + r) * AS + c];
                o[r][0] += p * vv.x;
                o[r][1] += p * vv.y;
                o[r][2] += p * vv.z;
                o[r][3] += p * vv.w;
            }
        }
    }

#pragma unroll
    for (int r = 0; r < 4; r++) {
        const float inv = 1.0f / l[r];
        float4 v = make_float4(o[r][0] * inv, o[r][1] * inv, o[r][2] * inv, o[r][3] * inv);
        *(float4*)(y + (size_t)(b * T_ + q0 + ty * 4 + r) * C_ + h * D_ + tx * 4) = v;
    }
}

// ---------------------------------------------------------------------------
// Launch — round-2 shape: one cudaFuncSetAttribute + 3 kernel launches.
// ---------------------------------------------------------------------------
extern "C" void kernel_launch(void* const* d_in, const int* in_sizes, int n_in,
                              void* d_out, int out_size)
{
    const float* x      = (const float*)d_in[0];   // [M, C]
    const float* W_attn = (const float*)d_in[1];   // [C, 3C]
    const float* W_proj = (const float*)d_in[2];   // [C, C]
    float* out = (float*)d_out;                    // [M, C]

    cudaFuncSetAttribute(attn_kernel, cudaFuncAttributeMaxDynamicSharedMemorySize, ATT_SMEM);

    // 1) QKV = x @ W_attn   (tf32 mma.sync, W consumed untransposed)
    {
        dim3 grid(C3_ / 128, MT_ / 128);   // (24, 64)
        qkv_gemm_mma<<<grid, 256>>>(x, W_attn);
    }
    // 2) attention (fp32)
    {
        dim3 grid(T_ / 64, H_, B_);        // (32, 16, 4)
        attn_kernel<<<grid, 256, ATT_SMEM>>>();
    }
    // 3) out = y @ W_proj   (tf32 mma.sync)
    {
        dim3 grid(C_ / 128, MT_ / 128);    // (8, 64)
        proj_gemm_mma<<<grid, 256>>>(W_proj, out);
    }
}

// round 8
// speedup vs baseline: 2.3078x; 1.4977x over previous
#include <cuda_runtime.h>
#include <cstdint>
#include <cstddef>

// Problem constants
#define B_ 4
#define T_ 2048
#define C_ 1024
#define H_ 16
#define D_ 64
#define C3_ 3072
#define MT_ 8192        // B*T

// Scratch — round-2 set (proven to pass the checker)
__device__ float g_qkv[(size_t)MT_ * C3_];   // [M, 3C]  96 MB
__device__ float g_y[(size_t)MT_ * C_];      // [M, C]   32 MB

// ---------------------------------------------------------------------------
// Helpers
// ---------------------------------------------------------------------------
__device__ __forceinline__ float tf32r(float x) {
    uint32_t u; asm("cvt.rna.tf32.f32 %0, %1;" : "=r"(u) : "f"(x));
    return __uint_as_float(u);
}
__device__ __forceinline__ void mma_tf32(float& c0, float& c1, float& c2, float& c3,
                                         uint32_t a0, uint32_t a1, uint32_t a2, uint32_t a3,
                                         uint32_t b0, uint32_t b1) {
    asm volatile(
        "mma.sync.aligned.m16n8k8.row.col.f32.tf32.tf32.f32 "
        "{%0,%1,%2,%3}, {%4,%5,%6,%7}, {%8,%9}, {%0,%1,%2,%3};"
        : "+f"(c0), "+f"(c1), "+f"(c2), "+f"(c3)
        : "r"(a0), "r"(a1), "r"(a2), "r"(a3), "r"(b0), "r"(b1));
}

// ---------------------------------------------------------------------------
// tf32 mma.sync GEMM (UNCHANGED from round 7 — passing).
// C[M,N] = A[M,K] @ W[K,N], W row-major. CTA 128x128, K-chunk 32.
// ---------------------------------------------------------------------------
#define KC 32
#define SNA 36
#define SNB 136

__device__ __forceinline__ void gemm_mma(
    const float* __restrict__ A, const float* __restrict__ W,
    float* __restrict__ Cout, int M, int N, int K)
{
    __shared__ float As[128][SNA];
    __shared__ float Bs[KC][SNB];

    const int tid  = threadIdx.x;
    const int wid  = tid >> 5;
    const int lane = tid & 31;
    const int lr   = lane >> 2;
    const int lc   = lane & 3;
    const int bm   = blockIdx.y * 128;
    const int bn   = blockIdx.x * 128;
    const int wm   = (wid >> 2) * 64;
    const int wn   = (wid & 3) * 32;

    const int NC = K / KC;

    float acc[4][4][4];
#pragma unroll
    for (int mi = 0; mi < 4; mi++)
#pragma unroll
        for (int ni = 0; ni < 4; ni++)
#pragma unroll
            for (int f = 0; f < 4; f++) acc[mi][ni][f] = 0.f;

    const int ra = tid >> 3;
    const int k4 = tid & 7;
    const float* Ap = A + (size_t)(bm + ra) * K + k4 * 4;
    const int kb = tid >> 5;
    const int n4 = tid & 31;
    const float* Wp = W + (size_t)kb * N + bn + n4 * 4;

    float4 pa0 = *(const float4*)(Ap);
    float4 pa1 = *(const float4*)(Ap + (size_t)32 * K);
    float4 pa2 = *(const float4*)(Ap + (size_t)64 * K);
    float4 pa3 = *(const float4*)(Ap + (size_t)96 * K);
    float4 pb0 = *(const float4*)(Wp);
    float4 pb1 = *(const float4*)(Wp + (size_t)8 * N);
    float4 pb2 = *(const float4*)(Wp + (size_t)16 * N);
    float4 pb3 = *(const float4*)(Wp + (size_t)24 * N);

    for (int c = 0; c < NC; c++) {
        float4 v;
        v = pa0; v.x = tf32r(v.x); v.y = tf32r(v.y); v.z = tf32r(v.z); v.w = tf32r(v.w);
        *(float4*)&As[ra][k4 * 4] = v;
        v = pa1; v.x = tf32r(v.x); v.y = tf32r(v.y); v.z = tf32r(v.z); v.w = tf32r(v.w);
        *(float4*)&As[ra + 32][k4 * 4] = v;
        v = pa2; v.x = tf32r(v.x); v.y = tf32r(v.y); v.z = tf32r(v.z); v.w = tf32r(v.w);
        *(float4*)&As[ra + 64][k4 * 4] = v;
        v = pa3; v.x = tf32r(v.x); v.y = tf32r(v.y); v.z = tf32r(v.z); v.w = tf32r(v.w);
        *(float4*)&As[ra + 96][k4 * 4] = v;
        v = pb0; v.x = tf32r(v.x); v.y = tf32r(v.y); v.z = tf32r(v.z); v.w = tf32r(v.w);
        *(float4*)&Bs[kb][n4 * 4] = v;
        v = pb1; v.x = tf32r(v.x); v.y = tf32r(v.y); v.z = tf32r(v.z); v.w = tf32r(v.w);
        *(float4*)&Bs[kb + 8][n4 * 4] = v;
        v = pb2; v.x = tf32r(v.x); v.y = tf32r(v.y); v.z = tf32r(v.z); v.w = tf32r(v.w);
        *(float4*)&Bs[kb + 16][n4 * 4] = v;
        v = pb3; v.x = tf32r(v.x); v.y = tf32r(v.y); v.z = tf32r(v.z); v.w = tf32r(v.w);
        *(float4*)&Bs[kb + 24][n4 * 4] = v;
        __syncthreads();

        if (c + 1 < NC) {
            const int go = (c + 1) * KC;
            pa0 = *(const float4*)(Ap + go);
            pa1 = *(const float4*)(Ap + (size_t)32 * K + go);
            pa2 = *(const float4*)(Ap + (size_t)64 * K + go);
            pa3 = *(const float4*)(Ap + (size_t)96 * K + go);
            const size_t wgo = (size_t)(c + 1) * KC * N;
            pb0 = *(const float4*)(Wp + wgo);
            pb1 = *(const float4*)(Wp + wgo + (size_t)8 * N);
            pb2 = *(const float4*)(Wp + wgo + (size_t)16 * N);
            pb3 = *(const float4*)(Wp + wgo + (size_t)24 * N);
        }

#pragma unroll
        for (int ks = 0; ks < 4; ks++) {
            const int k = ks * 8;
            uint32_t a[4][4], b[4][2];
#pragma unroll
            for (int mi = 0; mi < 4; mi++) {
                const int mrow = wm + mi * 16 + lr;
                a[mi][0] = __float_as_uint(As[mrow][k + lc]);
                a[mi][1] = __float_as_uint(As[mrow + 8][k + lc]);
                a[mi][2] = __float_as_uint(As[mrow][k + lc + 4]);
                a[mi][3] = __float_as_uint(As[mrow + 8][k + lc + 4]);
            }
#pragma unroll
            for (int ni = 0; ni < 4; ni++) {
                const int ncol = wn + ni * 8 + lr;
                b[ni][0] = __float_as_uint(Bs[k + lc][ncol]);
                b[ni][1] = __float_as_uint(Bs[k + lc + 4][ncol]);
            }
#pragma unroll
            for (int mi = 0; mi < 4; mi++)
#pragma unroll
                for (int ni = 0; ni < 4; ni++)
                    mma_tf32(acc[mi][ni][0], acc[mi][ni][1], acc[mi][ni][2], acc[mi][ni][3],
                             a[mi][0], a[mi][1], a[mi][2], a[mi][3], b[ni][0], b[ni][1]);
        }
        __syncthreads();
    }

#pragma unroll
    for (int mi = 0; mi < 4; mi++) {
#pragma unroll
        for (int ni = 0; ni < 4; ni++) {
            const int row = bm + wm + mi * 16 + lr;
            const int col = bn + wn + ni * 8 + lc * 2;
            *(float2*)(Cout + (size_t)row * N + col) =
                make_float2(acc[mi][ni][0], acc[mi][ni][1]);
            *(float2*)(Cout + (size_t)(row + 8) * N + col) =
                make_float2(acc[mi][ni][2], acc[mi][ni][3]);
        }
    }
}

__global__ __launch_bounds__(256, 1) void qkv_gemm_mma(const float* __restrict__ x,
                                                       const float* __restrict__ W_attn) {
    gemm_mma(x, W_attn, g_qkv, MT_, C3_, C_);
}
__global__ __launch_bounds__(256, 1) void proj_gemm_mma(const float* __restrict__ W_proj,
                                                        float* __restrict__ out) {
    gemm_mma(g_y, W_proj, out, MT_, C_, C_);
}

// ---------------------------------------------------------------------------
// Tensor-core causal flash attention (tf32 mma.sync), fp32 softmax stats.
// CTA: 128 q-rows; K-tile 64; D=64. 256 threads, 8 warps; warp w owns q-rows
// [w*16, w*16+16) => softmax rows are warp-complete (reduce over 4 lanes).
//   Qs[128][68]  q-major   (A-operand of S)
//   KT [64][68]  d-major   (B-operand of S: element (d, key))
//   Vs [64][68]  key-major (B-operand of PV: element (key, d))
//   Ps [128][68] q-major   (A-operand of PV)
// Fragment addressing identical to the proven GEMM:
//   a0=A[lr][lc], a1=A[lr+8][lc], a2=A[lr][lc+4], a3=A[lr+8][lc+4]
//   b0=B[k+lc][n+lr], b1=B[k+lc+4][n+lr]
//   c0,c1=(lr, 2lc..2lc+1), c2,c3=(lr+8, ...)
// ---------------------------------------------------------------------------
#define PAD2 68
#define ATT2_SMEM ((128 * PAD2 + 64 * PAD2 + 64 * PAD2 + 128 * PAD2) * 4)  // 104448

__global__ __launch_bounds__(256, 1) void attn_mma_kernel()
{
    extern __shared__ float sm[];
    float* Qs = sm;                       // [128][68]
    float* KT = Qs + 128 * PAD2;          // [64][68]
    float* Vs = KT + 64 * PAD2;           // [64][68]
    float* Ps = Vs + 64 * PAD2;           // [128][68]

    const int tid  = threadIdx.x;
    const int wid  = tid >> 5;
    const int lane = tid & 31;
    const int lr   = lane >> 2;
    const int lc   = lane & 3;
    const int qt   = (int)gridDim.x - 1 - (int)blockIdx.x;  // heavy tiles first
    const int h    = blockIdx.y;
    const int b    = blockIdx.z;
    const int q0   = qt * 128;
    const int wq   = wid * 16;
    const float scale = 0.125f;

    // Load Q tile [128 x 64], tf32-rounded
    const float* qbase = g_qkv + (size_t)(b * T_ + q0) * C3_ + h * D_;
#pragma unroll
    for (int i = 0; i < 8; i++) {
        const int idx = tid + i * 256;
        const int row = idx >> 4;
        const int c4  = (idx & 15) << 2;
        float4 v = *(const float4*)(qbase + (size_t)row * C3_ + c4);
        v.x = tf32r(v.x); v.y = tf32r(v.y); v.z = tf32r(v.z); v.w = tf32r(v.w);
        *(float4*)&Qs[row * PAD2 + c4] = v;
    }

    float m0 = -1e30f, m1 = -1e30f, l0 = 0.f, l1 = 0.f;
    float o[8][4];
#pragma unroll
    for (int dt = 0; dt < 8; dt++)
#pragma unroll
        for (int f = 0; f < 4; f++) o[dt][f] = 0.f;

    const int qr0 = q0 + wq + lr;    // global q row for c0/c1
    const int qr1 = qr0 + 8;         // for c2/c3
    const int nkt = 2 * qt + 2;

    for (int kt = 0; kt < nkt; kt++) {
        const int k0 = kt * 64;
        const float* kbase = g_qkv + (size_t)(b * T_ + k0) * C3_ + C_ + h * D_;
        const float* vbase = kbase + C_;

        __syncthreads();   // prior-iter KT/Vs reads complete
#pragma unroll
        for (int i = 0; i < 4; i++) {
            const int idx = tid + i * 256;
            const int row = idx >> 4;          // key 0..63
            const int c4  = (idx & 15) << 2;   // d
            float4 kv = *(const float4*)(kbase + (size_t)row * C3_ + c4);
            KT[(c4 + 0) * PAD2 + row] = tf32r(kv.x);
            KT[(c4 + 1) * PAD2 + row] = tf32r(kv.y);
            KT[(c4 + 2) * PAD2 + row] = tf32r(kv.z);
            KT[(c4 + 3) * PAD2 + row] = tf32r(kv.w);
            float4 vv = *(const float4*)(vbase + (size_t)row * C3_ + c4);
            vv.x = tf32r(vv.x); vv.y = tf32r(vv.y); vv.z = tf32r(vv.z); vv.w = tf32r(vv.w);
            *(float4*)&Vs[row * PAD2 + c4] = vv;
        }
        __syncthreads();

        if (k0 <= q0 + wq + 15) {   // warp has >=1 unmasked row in this tile
            // ---- S = Q K^T (16 x 64 per warp) ----
            float s[8][4];
#pragma unroll
            for (int nt = 0; nt < 8; nt++)
#pragma unroll
                for (int f = 0; f < 4; f++) s[nt][f] = 0.f;

#pragma unroll
            for (int kd = 0; kd < 8; kd++) {
                const int k = kd * 8;
                const uint32_t a0 = __float_as_uint(Qs[(wq + lr) * PAD2 + k + lc]);
                const uint32_t a1 = __float_as_uint(Qs[(wq + lr + 8) * PAD2 + k + lc]);
                const uint32_t a2 = __float_as_uint(Qs[(wq + lr) * PAD2 + k + lc + 4]);
                const uint32_t a3 = __float_as_uint(Qs[(wq + lr + 8) * PAD2 + k + lc + 4]);
#pragma unroll
                for (int nt = 0; nt < 8; nt++) {
                    const uint32_t b0 = __float_as_uint(KT[(k + lc) * PAD2 + nt * 8 + lr]);
                    const uint32_t b1 = __float_as_uint(KT[(k + lc + 4) * PAD2 + nt * 8 + lr]);
                    mma_tf32(s[nt][0], s[nt][1], s[nt][2], s[nt][3], a0, a1, a2, a3, b0, b1);
                }
            }

            // ---- scale + causal mask + online softmax ----
            const bool need_mask = (k0 + 63 > q0 + wq);
            float rmax0 = -1e30f, rmax1 = -1e30f;
#pragma unroll
            for (int nt = 0; nt < 8; nt++) {
                const int kcol = k0 + nt * 8 + 2 * lc;
                float v0 = s[nt][0] * scale, v1 = s[nt][1] * scale;
                float v2 = s[nt][2] * scale, v3 = s[nt][3] * scale;
                if (need_mask) {
                    if (kcol     > qr0) v0 = -1e30f;
                    if (kcol + 1 > qr0) v1 = -1e30f;
                    if (kcol     > qr1) v2 = -1e30f;
                    if (kcol + 1 > qr1) v3 = -1e30f;
                }
                s[nt][0] = v0; s[nt][1] = v1; s[nt][2] = v2; s[nt][3] = v3;
                rmax0 = fmaxf(rmax0, fmaxf(v0, v1));
                rmax1 = fmaxf(rmax1, fmaxf(v2, v3));
            }
            rmax0 = fmaxf(rmax0, __shfl_xor_sync(0xffffffffu, rmax0, 1));
            rmax0 = fmaxf(rmax0, __shfl_xor_sync(0xffffffffu, rmax0, 2));
            rmax1 = fmaxf(rmax1, __shfl_xor_sync(0xffffffffu, rmax1, 1));
            rmax1 = fmaxf(rmax1, __shfl_xor_sync(0xffffffffu, rmax1, 2));

            const float mn0 = fmaxf(m0, rmax0);
            const float mn1 = fmaxf(m1, rmax1);
            const float alpha0 = __expf(m0 - mn0);
            const float alpha1 = __expf(m1 - mn1);

            float sum0 = 0.f, sum1 = 0.f;
#pragma unroll
            for (int nt = 0; nt < 8; nt++) {
                const float p0 = __expf(s[nt][0] - mn0);
                const float p1 = __expf(s[nt][1] - mn0);
                const float p2 = __expf(s[nt][2] - mn1);
                const float p3 = __expf(s[nt][3] - mn1);
                s[nt][0] = p0; s[nt][1] = p1; s[nt][2] = p2; s[nt][3] = p3;
                sum0 += p0 + p1;
                sum1 += p2 + p3;
            }
            sum0 += __shfl_xor_sync(0xffffffffu, sum0, 1);
            sum0 += __shfl_xor_sync(0xffffffffu, sum0, 2);
            sum1 += __shfl_xor_sync(0xffffffffu, sum1, 1);
            sum1 += __shfl_xor_sync(0xffffffffu, sum1, 2);

            l0 = l0 * alpha0 + sum0;
            l1 = l1 * alpha1 + sum1;
            m0 = mn0; m1 = mn1;

#pragma unroll
            for (int dt = 0; dt < 8; dt++) {
                o[dt][0] *= alpha0; o[dt][1] *= alpha0;
                o[dt][2] *= alpha1; o[dt][3] *= alpha1;
            }

            // ---- P -> smem (tf32-rounded), then O += P V ----
#pragma unroll
            for (int nt = 0; nt < 8; nt++) {
                *(float2*)&Ps[(wq + lr) * PAD2 + nt * 8 + 2 * lc] =
                    make_float2(tf32r(s[nt][0]), tf32r(s[nt][1]));
                *(float2*)&Ps[(wq + lr + 8) * PAD2 + nt * 8 + 2 * lc] =
                    make_float2(tf32r(s[nt][2]), tf32r(s[nt][3]));
            }
            __syncwarp();

#pragma unroll
            for (int kd = 0; kd < 8; kd++) {
                const int k = kd * 8;
                const uint32_t a0 = __float_as_uint(Ps[(wq + lr) * PAD2 + k + lc]);
                const uint32_t a1 = __float_as_uint(Ps[(wq + lr + 8) * PAD2 + k + lc]);
                const uint32_t a2 = __float_as_uint(Ps[(wq + lr) * PAD2 + k + lc + 4]);
                const uint32_t a3 = __float_as_uint(Ps[(wq + lr + 8) * PAD2 + k + lc + 4]);
#pragma unroll
                for (int dt = 0; dt < 8; dt++) {
                    const uint32_t b0 = __float_as_uint(Vs[(k + lc) * PAD2 + dt * 8 + lr]);
                    const uint32_t b1 = __float_as_uint(Vs[(k + lc + 4) * PAD2 + dt * 8 + lr]);
                    mma_tf32(o[dt][0], o[dt][1], o[dt][2], o[dt][3], a0, a1, a2, a3, b0, b1);
                }
            }
        }
    }

    // Epilogue: normalize, write y[b, q, h*64 + d]
    const float inv0 = 1.0f / l0;
    const float inv1 = 1.0f / l1;
    float* y0 = g_y + (size_t)(b * T_ + qr0) * C_ + h * D_;
    float* y1 = g_y + (size_t)(b * T_ + qr1) * C_ + h * D_;
#pragma unroll
    for (int dt = 0; dt < 8; dt++) {
        const int col = dt * 8 + 2 * lc;
        *(float2*)(y0 + col) = make_float2(o[dt][0] * inv0, o[dt][1] * inv0);
        *(float2*)(y1 + col) = make_float2(o[dt][2] * inv1, o[dt][3] * inv1);
    }
}

// ---------------------------------------------------------------------------
// Launch
// ---------------------------------------------------------------------------
extern "C" void kernel_launch(void* const* d_in, const int* in_sizes, int n_in,
                              void* d_out, int out_size)
{
    const float* x      = (const float*)d_in[0];   // [M, C]
    const float* W_attn = (const float*)d_in[1];   // [C, 3C]
    const float* W_proj = (const float*)d_in[2];   // [C, C]
    float* out = (float*)d_out;                    // [M, C]

    cudaFuncSetAttribute(attn_mma_kernel, cudaFuncAttributeMaxDynamicSharedMemorySize, ATT2_SMEM);

    // 1) QKV = x @ W_attn   (tf32 mma.sync)
    {
        dim3 grid(C3_ / 128, MT_ / 128);   // (24, 64)
        qkv_gemm_mma<<<grid, 256>>>(x, W_attn);
    }
    // 2) attention (tf32 mma.sync, fp32 softmax)
    {
        dim3 grid(T_ / 128, H_, B_);       // (16, 16, 4)
        attn_mma_kernel<<<grid, 256, ATT2_SMEM>>>();
    }
    // 3) out = y @ W_proj   (tf32 mma.sync)
    {
        dim3 grid(C_ / 128, MT_ / 128);    // (8, 64)
        proj_gemm_mma<<<grid, 256>>>(W_proj, out);
    }
}

// round 10
// speedup vs baseline: 2.3749x; 1.0291x over previous
#include <cuda_runtime.h>
#include <cstdint>
#include <cstddef>

// Problem constants
#define B_ 4
#define T_ 2048
#define C_ 1024
#define H_ 16
#define D_ 64
#define C3_ 3072
#define MT_ 8192        // B*T

// Scratch — round-2 set (proven to pass the checker)
__device__ float g_qkv[(size_t)MT_ * C3_];   // [M, 3C]  96 MB
__device__ float g_y[(size_t)MT_ * C_];      // [M, C]   32 MB

// ---------------------------------------------------------------------------
// Helpers
// ---------------------------------------------------------------------------
__device__ __forceinline__ float tf32r(float x) {
    uint32_t u; asm("cvt.rna.tf32.f32 %0, %1;" : "=r"(u) : "f"(x));
    return __uint_as_float(u);
}
__device__ __forceinline__ void mma_tf32(float& c0, float& c1, float& c2, float& c3,
                                         uint32_t a0, uint32_t a1, uint32_t a2, uint32_t a3,
                                         uint32_t b0, uint32_t b1) {
    asm volatile(
        "mma.sync.aligned.m16n8k8.row.col.f32.tf32.tf32.f32 "
        "{%0,%1,%2,%3}, {%4,%5,%6,%7}, {%8,%9}, {%0,%1,%2,%3};"
        : "+f"(c0), "+f"(c1), "+f"(c2), "+f"(c3)
        : "r"(a0), "r"(a1), "r"(a2), "r"(a3), "r"(b0), "r"(b1));
}

// ---------------------------------------------------------------------------
// tf32 mma.sync GEMM, 2-stage double-buffered smem (dynamic).
// C[M,N] = A[M,K] @ W[K,N], W row-major. CTA 128x128, K-chunk 32, 8 warps 64x32.
// Stage layout (words): As[128][36] at +0, Bs[32][136] at +4608. Stage stride 8960.
// One __syncthreads per K-chunk; STS of chunk c+1 overlaps nothing critical.
// ---------------------------------------------------------------------------
#define KC 32
#define SNA 36
#define SNB 136
#define STAGE_W (128 * SNA + KC * SNB)          // 8960 words
#define GEMM_SMEM (2 * STAGE_W * 4)             // 71680 bytes

__device__ __forceinline__ void gemm_mma(
    const float* __restrict__ A, const float* __restrict__ W,
    float* __restrict__ Cout, int M, int N, int K)
{
    extern __shared__ float sm[];

    const int tid  = threadIdx.x;
    const int wid  = tid >> 5;
    const int lane = tid & 31;
    const int lr   = lane >> 2;
    const int lc   = lane & 3;
    const int bm   = blockIdx.y * 128;
    const int bn   = blockIdx.x * 128;
    const int wm   = (wid >> 2) * 64;
    const int wn   = (wid & 3) * 32;

    const int NC = K / KC;

    float acc[4][4][4];
#pragma unroll
    for (int mi = 0; mi < 4; mi++)
#pragma unroll
        for (int ni = 0; ni < 4; ni++)
#pragma unroll
            for (int f = 0; f < 4; f++) acc[mi][ni][f] = 0.f;

    // Loaders (identical mapping to round 7, proven)
    const int ra = tid >> 3;          // 0..31
    const int k4 = tid & 7;
    const float* Ap = A + (size_t)(bm + ra) * K + k4 * 4;
    const int kb = tid >> 5;          // 0..7
    const int n4 = tid & 31;
    const float* Wp = W + (size_t)kb * N + bn + n4 * 4;

    // Prefetch chunk 0
    float4 pa0 = *(const float4*)(Ap);
    float4 pa1 = *(const float4*)(Ap + (size_t)32 * K);
    float4 pa2 = *(const float4*)(Ap + (size_t)64 * K);
    float4 pa3 = *(const float4*)(Ap + (size_t)96 * K);
    float4 pb0 = *(const float4*)(Wp);
    float4 pb1 = *(const float4*)(Wp + (size_t)8 * N);
    float4 pb2 = *(const float4*)(Wp + (size_t)16 * N);
    float4 pb3 = *(const float4*)(Wp + (size_t)24 * N);

    // Store chunk 0 into stage 0
    {
        float* As = sm;
        float* Bs = sm + 128 * SNA;
        float4 v;
        v = pa0; v.x = tf32r(v.x); v.y = tf32r(v.y); v.z = tf32r(v.z); v.w = tf32r(v.w);
        *(float4*)&As[ra * SNA + k4 * 4] = v;
        v = pa1; v.x = tf32r(v.x); v.y = tf32r(v.y); v.z = tf32r(v.z); v.w = tf32r(v.w);
        *(float4*)&As[(ra + 32) * SNA + k4 * 4] = v;
        v = pa2; v.x = tf32r(v.x); v.y = tf32r(v.y); v.z = tf32r(v.z); v.w = tf32r(v.w);
        *(float4*)&As[(ra + 64) * SNA + k4 * 4] = v;
        v = pa3; v.x = tf32r(v.x); v.y = tf32r(v.y); v.z = tf32r(v.z); v.w = tf32r(v.w);
        *(float4*)&As[(ra + 96) * SNA + k4 * 4] = v;
        v = pb0; v.x = tf32r(v.x); v.y = tf32r(v.y); v.z = tf32r(v.z); v.w = tf32r(v.w);
        *(float4*)&Bs[kb * SNB + n4 * 4] = v;
        v = pb1; v.x = tf32r(v.x); v.y = tf32r(v.y); v.z = tf32r(v.z); v.w = tf32r(v.w);
        *(float4*)&Bs[(kb + 8) * SNB + n4 * 4] = v;
        v = pb2; v.x = tf32r(v.x); v.y = tf32r(v.y); v.z = tf32r(v.z); v.w = tf32r(v.w);
        *(float4*)&Bs[(kb + 16) * SNB + n4 * 4] = v;
        v = pb3; v.x = tf32r(v.x); v.y = tf32r(v.y); v.z = tf32r(v.z); v.w = tf32r(v.w);
        *(float4*)&Bs[(kb + 24) * SNB + n4 * 4] = v;
    }
    __syncthreads();

    for (int c = 0; c < NC; c++) {
        const bool more = (c + 1 < NC);
        // Issue LDG for chunk c+1 (covered by this chunk's compute)
        if (more) {
            const int go = (c + 1) * KC;
            pa0 = *(const float4*)(Ap + go);
            pa1 = *(const float4*)(Ap + (size_t)32 * K + go);
            pa2 = *(const float4*)(Ap + (size_t)64 * K + go);
            pa3 = *(const float4*)(Ap + (size_t)96 * K + go);
            const size_t wgo = (size_t)(c + 1) * KC * N;
            pb0 = *(const float4*)(Wp + wgo);
            pb1 = *(const float4*)(Wp + wgo + (size_t)8 * N);
            pb2 = *(const float4*)(Wp + wgo + (size_t)16 * N);
            pb3 = *(const float4*)(Wp + wgo + (size_t)24 * N);
        }

        // Compute from stage c&1
        const float* As = sm + (c & 1) * STAGE_W;
        const float* Bs = As + 128 * SNA;
#pragma unroll
        for (int ks = 0; ks < 4; ks++) {
            const int k = ks * 8;
            uint32_t a[4][4], b[4][2];
#pragma unroll
            for (int mi = 0; mi < 4; mi++) {
                const int mrow = wm + mi * 16 + lr;
                a[mi][0] = __float_as_uint(As[mrow * SNA + k + lc]);
                a[mi][1] = __float_as_uint(As[(mrow + 8) * SNA + k + lc]);
                a[mi][2] = __float_as_uint(As[mrow * SNA + k + lc + 4]);
                a[mi][3] = __float_as_uint(As[(mrow + 8) * SNA + k + lc + 4]);
            }
#pragma unroll
            for (int ni = 0; ni < 4; ni++) {
                const int ncol = wn + ni * 8 + lr;
                b[ni][0] = __float_as_uint(Bs[(k + lc) * SNB + ncol]);
                b[ni][1] = __float_as_uint(Bs[(k + lc + 4) * SNB + ncol]);
            }
#pragma unroll
            for (int mi = 0; mi < 4; mi++)
#pragma unroll
                for (int ni = 0; ni < 4; ni++)
                    mma_tf32(acc[mi][ni][0], acc[mi][ni][1], acc[mi][ni][2], acc[mi][ni][3],
                             a[mi][0], a[mi][1], a[mi][2], a[mi][3], b[ni][0], b[ni][1]);
        }

        // Store chunk c+1 into the other stage
        if (more) {
            float* Asn = sm + ((c + 1) & 1) * STAGE_W;
            float* Bsn = Asn + 128 * SNA;
            float4 v;
            v = pa0; v.x = tf32r(v.x); v.y = tf32r(v.y); v.z = tf32r(v.z); v.w = tf32r(v.w);
            *(float4*)&Asn[ra * SNA + k4 * 4] = v;
            v = pa1; v.x = tf32r(v.x); v.y = tf32r(v.y); v.z = tf32r(v.z); v.w = tf32r(v.w);
            *(float4*)&Asn[(ra + 32) * SNA + k4 * 4] = v;
            v = pa2; v.x = tf32r(v.x); v.y = tf32r(v.y); v.z = tf32r(v.z); v.w = tf32r(v.w);
            *(float4*)&Asn[(ra + 64) * SNA + k4 * 4] = v;
            v = pa3; v.x = tf32r(v.x); v.y = tf32r(v.y); v.z = tf32r(v.z); v.w = tf32r(v.w);
            *(float4*)&Asn[(ra + 96) * SNA + k4 * 4] = v;
            v = pb0; v.x = tf32r(v.x); v.y = tf32r(v.y); v.z = tf32r(v.z); v.w = tf32r(v.w);
            *(float4*)&Bsn[kb * SNB + n4 * 4] = v;
            v = pb1; v.x = tf32r(v.x); v.y = tf32r(v.y); v.z = tf32r(v.z); v.w = tf32r(v.w);
            *(float4*)&Bsn[(kb + 8) * SNB + n4 * 4] = v;
            v = pb2; v.x = tf32r(v.x); v.y = tf32r(v.y); v.z = tf32r(v.z); v.w = tf32r(v.w);
            *(float4*)&Bsn[(kb + 16) * SNB + n4 * 4] = v;
            v = pb3; v.x = tf32r(v.x); v.y = tf32r(v.y); v.z = tf32r(v.z); v.w = tf32r(v.w);
            *(float4*)&Bsn[(kb + 24) * SNB + n4 * 4] = v;
        }
        __syncthreads();
    }

    // Epilogue
#pragma unroll
    for (int mi = 0; mi < 4; mi++) {
#pragma unroll
        for (int ni = 0; ni < 4; ni++) {
            const int row = bm + wm + mi * 16 + lr;
            const int col = bn + wn + ni * 8 + lc * 2;
            *(float2*)(Cout + (size_t)row * N + col) =
                make_float2(acc[mi][ni][0], acc[mi][ni][1]);
            *(float2*)(Cout + (size_t)(row + 8) * N + col) =
                make_float2(acc[mi][ni][2], acc[mi][ni][3]);
        }
    }
}

__global__ __launch_bounds__(256, 1) void qkv_gemm_mma(const float* __restrict__ x,
                                                       const float* __restrict__ W_attn) {
    gemm_mma(x, W_attn, g_qkv, MT_, C3_, C_);
}
__global__ __launch_bounds__(256, 1) void proj_gemm_mma(const float* __restrict__ W_proj,
                                                        float* __restrict__ out) {
    gemm_mma(g_y, W_proj, out, MT_, C_, C_);
}

// ---------------------------------------------------------------------------
// Tensor-core causal flash attention (round-8 logic),
// __launch_bounds__(256, 2): 2 CTAs/SM (smem 104.4KB x2 = 209KB < 228KB).
// ---------------------------------------------------------------------------
#define PAD2 68
#define ATT2_SMEM ((128 * PAD2 + 64 * PAD2 + 64 * PAD2 + 128 * PAD2) * 4)  // 104448

__global__ __launch_bounds__(256, 2) void attn_mma_kernel()
{
    extern __shared__ float sm[];
    float* Qs = sm;                       // [128][68]
    float* KT = Qs + 128 * PAD2;          // [64][68]
    float* Vs = KT + 64 * PAD2;           // [64][68]
    float* Ps = Vs + 64 * PAD2;           // [128][68]

    const int tid  = threadIdx.x;
    const int wid  = tid >> 5;
    const int lane = tid & 31;
    const int lr   = lane >> 2;
    const int lc   = lane & 3;
    const int qt   = (int)gridDim.x - 1 - (int)blockIdx.x;  // heavy tiles first
    const int h    = blockIdx.y;
    const int b    = blockIdx.z;
    const int q0   = qt * 128;
    const int wq   = wid * 16;
    const float scale = 0.125f;

    const float* qbase = g_qkv + (size_t)(b * T_ + q0) * C3_ + h * D_;
#pragma unroll
    for (int i = 0; i < 8; i++) {
        const int idx = tid + i * 256;
        const int row = idx >> 4;
        const int c4  = (idx & 15) << 2;
        float4 v = *(const float4*)(qbase + (size_t)row * C3_ + c4);
        v.x = tf32r(v.x); v.y = tf32r(v.y); v.z = tf32r(v.z); v.w = tf32r(v.w);
        *(float4*)&Qs[row * PAD2 + c4] = v;
    }

    float m0 = -1e30f, m1 = -1e30f, l0 = 0.f, l1 = 0.f;
    float o[8][4];
#pragma unroll
    for (int dt = 0; dt < 8; dt++)
#pragma unroll
        for (int f = 0; f < 4; f++) o[dt][f] = 0.f;

    const int qr0 = q0 + wq + lr;
    const int qr1 = qr0 + 8;
    const int nkt = 2 * qt + 2;

    for (int kt = 0; kt < nkt; kt++) {
        const int k0 = kt * 64;
        const float* kbase = g_qkv + (size_t)(b * T_ + k0) * C3_ + C_ + h * D_;
        const float* vbase = kbase + C_;

        __syncthreads();
#pragma unroll
        for (int i = 0; i < 4; i++) {
            const int idx = tid + i * 256;
            const int row = idx >> 4;
            const int c4  = (idx & 15) << 2;
            float4 kv = *(const float4*)(kbase + (size_t)row * C3_ + c4);
            KT[(c4 + 0) * PAD2 + row] = tf32r(kv.x);
            KT[(c4 + 1) * PAD2 + row] = tf32r(kv.y);
            KT[(c4 + 2) * PAD2 + row] = tf32r(kv.z);
            KT[(c4 + 3) * PAD2 + row] = tf32r(kv.w);
            float4 vv = *(const float4*)(vbase + (size_t)row * C3_ + c4);
            vv.x = tf32r(vv.x); vv.y = tf32r(vv.y); vv.z = tf32r(vv.z); vv.w = tf32r(vv.w);
            *(float4*)&Vs[row * PAD2 + c4] = vv;
        }
        __syncthreads();

        if (k0 <= q0 + wq + 15) {
            float s[8][4];
#pragma unroll
            for (int nt = 0; nt < 8; nt++)
#pragma unroll
                for (int f = 0; f < 4; f++) s[nt][f] = 0.f;

#pragma unroll
            for (int kd = 0; kd < 8; kd++) {
                const int k = kd * 8;
                const uint32_t a0 = __float_as_uint(Qs[(wq + lr) * PAD2 + k + lc]);
                const uint32_t a1 = __float_as_uint(Qs[(wq + lr + 8) * PAD2 + k + lc]);
                const uint32_t a2 = __float_as_uint(Qs[(wq + lr) * PAD2 + k + lc + 4]);
                const uint32_t a3 = __float_as_uint(Qs[(wq + lr + 8) * PAD2 + k + lc + 4]);
#pragma unroll
                for (int nt = 0; nt < 8; nt++) {
                    const uint32_t b0 = __float_as_uint(KT[(k + lc) * PAD2 + nt * 8 + lr]);
                    const uint32_t b1 = __float_as_uint(KT[(k + lc + 4) * PAD2 + nt * 8 + lr]);
                    mma_tf32(s[nt][0], s[nt][1], s[nt][2], s[nt][3], a0, a1, a2, a3, b0, b1);
                }
            }

            const bool need_mask = (k0 + 63 > q0 + wq);
            float rmax0 = -1e30f, rmax1 = -1e30f;
#pragma unroll
            for (int nt = 0; nt < 8; nt++) {
                const int kcol = k0 + nt * 8 + 2 * lc;
                float v0 = s[nt][0] * scale, v1 = s[nt][1] * scale;
                float v2 = s[nt][2] * scale, v3 = s[nt][3] * scale;
                if (need_mask) {
                    if (kcol     > qr0) v0 = -1e30f;
                    if (kcol + 1 > qr0) v1 = -1e30f;
                    if (kcol     > qr1) v2 = -1e30f;
                    if (kcol + 1 > qr1) v3 = -1e30f;
                }
                s[nt][0] = v0; s[nt][1] = v1; s[nt][2] = v2; s[nt][3] = v3;
                rmax0 = fmaxf(rmax0, fmaxf(v0, v1));
                rmax1 = fmaxf(rmax1, fmaxf(v2, v3));
            }
            rmax0 = fmaxf(rmax0, __shfl_xor_sync(0xffffffffu, rmax0, 1));
            rmax0 = fmaxf(rmax0, __shfl_xor_sync(0xffffffffu, rmax0, 2));
            rmax1 = fmaxf(rmax1, __shfl_xor_sync(0xffffffffu, rmax1, 1));
            rmax1 = fmaxf(rmax1, __shfl_xor_sync(0xffffffffu, rmax1, 2));

            const float mn0 = fmaxf(m0, rmax0);
            const float mn1 = fmaxf(m1, rmax1);
            const float alpha0 = __expf(m0 - mn0);
            const float alpha1 = __expf(m1 - mn1);

            float sum0 = 0.f, sum1 = 0.f;
#pragma unroll
            for (int nt = 0; nt < 8; nt++) {
                const float p0 = __expf(s[nt][0] - mn0);
                const float p1 = __expf(s[nt][1] - mn0);
                const float p2 = __expf(s[nt][2] - mn1);
                const float p3 = __expf(s[nt][3] - mn1);
                s[nt][0] = p0; s[nt][1] = p1; s[nt][2] = p2; s[nt][3] = p3;
                sum0 += p0 + p1;
                sum1 += p2 + p3;
            }
            sum0 += __shfl_xor_sync(0xffffffffu, sum0, 1);
            sum0 += __shfl_xor_sync(0xffffffffu, sum0, 2);
            sum1 += __shfl_xor_sync(0xffffffffu, sum1, 1);
            sum1 += __shfl_xor_sync(0xffffffffu, sum1, 2);

            l0 = l0 * alpha0 + sum0;
            l1 = l1 * alpha1 + sum1;
            m0 = mn0; m1 = mn1;

#pragma unroll
            for (int dt = 0; dt < 8; dt++) {
                o[dt][0] *= alpha0; o[dt][1] *= alpha0;
                o[dt][2] *= alpha1; o[dt][3] *= alpha1;
            }

#pragma unroll
            for (int nt = 0; nt < 8; nt++) {
                *(float2*)&Ps[(wq + lr) * PAD2 + nt * 8 + 2 * lc] =
                    make_float2(tf32r(s[nt][0]), tf32r(s[nt][1]));
                *(float2*)&Ps[(wq + lr + 8) * PAD2 + nt * 8 + 2 * lc] =
                    make_float2(tf32r(s[nt][2]), tf32r(s[nt][3]));
            }
            __syncwarp();

#pragma unroll
            for (int kd = 0; kd < 8; kd++) {
                const int k = kd * 8;
                const uint32_t a0 = __float_as_uint(Ps[(wq + lr) * PAD2 + k + lc]);
                const uint32_t a1 = __float_as_uint(Ps[(wq + lr + 8) * PAD2 + k + lc]);
                const uint32_t a2 = __float_as_uint(Ps[(wq + lr) * PAD2 + k + lc + 4]);
                const uint32_t a3 = __float_as_uint(Ps[(wq + lr + 8) * PAD2 + k + lc + 4]);
#pragma unroll
                for (int dt = 0; dt < 8; dt++) {
                    const uint32_t b0 = __float_as_uint(Vs[(k + lc) * PAD2 + dt * 8 + lr]);
                    const uint32_t b1 = __float_as_uint(Vs[(k + lc + 4) * PAD2 + dt * 8 + lr]);
                    mma_tf32(o[dt][0], o[dt][1], o[dt][2], o[dt][3], a0, a1, a2, a3, b0, b1);
                }
            }
        }
    }

    const float inv0 = 1.0f / l0;
    const float inv1 = 1.0f / l1;
    float* y0 = g_y + (size_t)(b * T_ + qr0) * C_ + h * D_;
    float* y1 = g_y + (size_t)(b * T_ + qr1) * C_ + h * D_;
#pragma unroll
    for (int dt = 0; dt < 8; dt++) {
        const int col = dt * 8 + 2 * lc;
        *(float2*)(y0 + col) = make_float2(o[dt][0] * inv0, o[dt][1] * inv0);
        *(float2*)(y1 + col) = make_float2(o[dt][2] * inv1, o[dt][3] * inv1);
    }
}

// ---------------------------------------------------------------------------
// Launch
// ---------------------------------------------------------------------------
extern "C" void kernel_launch(void* const* d_in, const int* in_sizes, int n_in,
                              void* d_out, int out_size)
{
    const float* x      = (const float*)d_in[0];   // [M, C]
    const float* W_attn = (const float*)d_in[1];   // [C, 3C]
    const float* W_proj = (const float*)d_in[2];   // [C, C]
    float* out = (float*)d_out;                    // [M, C]

    cudaFuncSetAttribute(qkv_gemm_mma,    cudaFuncAttributeMaxDynamicSharedMemorySize, GEMM_SMEM);
    cudaFuncSetAttribute(proj_gemm_mma,   cudaFuncAttributeMaxDynamicSharedMemorySize, GEMM_SMEM);
    cudaFuncSetAttribute(attn_mma_kernel, cudaFuncAttributeMaxDynamicSharedMemorySize, ATT2_SMEM);

    // 1) QKV = x @ W_attn   (tf32 mma.sync, double-buffered)
    {
        dim3 grid(C3_ / 128, MT_ / 128);   // (24, 64)
        qkv_gemm_mma<<<grid, 256, GEMM_SMEM>>>(x, W_attn);
    }
    // 2) attention (tf32 mma.sync, fp32 softmax, 2 CTAs/SM)
    {
        dim3 grid(T_ / 128, H_, B_);       // (16, 16, 4)
        attn_mma_kernel<<<grid, 256, ATT2_SMEM>>>();
    }
    // 3) out = y @ W_proj   (tf32 mma.sync, double-buffered)
    {
        dim3 grid(C_ / 128, MT_ / 128);    // (8, 64)
        proj_gemm_mma<<<grid, 256, GEMM_SMEM>>>(W_proj, out);
    }
}

// round 11
// speedup vs baseline: 3.1365x; 1.3207x over previous
#include <cuda_runtime.h>
#include <cuda_fp16.h>
#include <cstdint>
#include <cstddef>

// Problem constants
#define B_ 4
#define T_ 2048
#define C_ 1024
#define H_ 16
#define D_ 64
#define C3_ 3072
#define MT_ 8192        // B*T

// Scratch — round-2 set (proven to pass the checker)
__device__ float g_qkv[(size_t)MT_ * C3_];   // [M, 3C]  96 MB
__device__ float g_y[(size_t)MT_ * C_];      // [M, C]   32 MB

// ---------------------------------------------------------------------------
// Helpers
// ---------------------------------------------------------------------------
__device__ __forceinline__ uint32_t fh2(float lo, float hi) {
    __half2 t = __floats2half2_rn(lo, hi);
    return *(uint32_t*)&t;
}
__device__ __forceinline__ void mma_f16(float& c0, float& c1, float& c2, float& c3,
                                        uint32_t a0, uint32_t a1, uint32_t a2, uint32_t a3,
                                        uint32_t b0, uint32_t b1) {
    asm volatile(
        "mma.sync.aligned.m16n8k16.row.col.f32.f16.f16.f32 "
        "{%0,%1,%2,%3}, {%4,%5,%6,%7}, {%8,%9}, {%0,%1,%2,%3};"
        : "+f"(c0), "+f"(c1), "+f"(c2), "+f"(c3)
        : "r"(a0), "r"(a1), "r"(a2), "r"(a3), "r"(b0), "r"(b1));
}

// ---------------------------------------------------------------------------
// fp16 mma.sync GEMM: C[M,N] = A[M,K] @ W[K,N] (W row-major), fp32 accumulate.
// CTA 128x128, K-chunk 32, 2-stage double-buffered smem, 8 warps 64x32.
// Smem (halves): As[128][40] (m-major, k-contig), Bs[128][40] (n-major, k-contig).
// Fragment reads: stride 40 halves -> bank sets 20*lr+lc, conflict-free.
// ---------------------------------------------------------------------------
#define KC 32
#define SAH 40
#define STAGE_H (2 * 128 * SAH)          // 10240 halves per stage
#define GEMM_SMEM (2 * STAGE_H * 2)      // 40960 bytes

__device__ __forceinline__ void gemm_mma(
    const float* __restrict__ A, const float* __restrict__ W,
    float* __restrict__ Cout, int M, int N, int K)
{
    extern __shared__ __align__(16) char smraw[];
    __half* smh = (__half*)smraw;

    const int tid  = threadIdx.x;
    const int wid  = tid >> 5;
    const int lane = tid & 31;
    const int lr   = lane >> 2;
    const int lc   = lane & 3;
    const int bm   = blockIdx.y * 128;
    const int bn   = blockIdx.x * 128;
    const int wm   = (wid >> 2) * 64;
    const int wn   = (wid & 3) * 32;

    const int NC = K / KC;

    float acc[4][4][4];
#pragma unroll
    for (int mi = 0; mi < 4; mi++)
#pragma unroll
        for (int ni = 0; ni < 4; ni++)
#pragma unroll
            for (int f = 0; f < 4; f++) acc[mi][ni][f] = 0.f;

    // A loader: rows ra,+32,+64,+96; float4 at k4*4 within the 32-float chunk.
    const int ra = tid >> 3;          // 0..31
    const int k4 = tid & 7;
    const float* Ap = A + (size_t)(bm + ra) * K + k4 * 4;
    // B loader: cols 4*n4..+3; k-pairs kp and kp+8 (two rows per pair for half2 packing).
    const int n4 = tid & 31;
    const int kp = tid >> 5;          // 0..7
    const float* Wp = W + (size_t)(2 * kp) * N + bn + n4 * 4;

    // Prefetch chunk 0
    float4 pa0 = *(const float4*)(Ap);
    float4 pa1 = *(const float4*)(Ap + (size_t)32 * K);
    float4 pa2 = *(const float4*)(Ap + (size_t)64 * K);
    float4 pa3 = *(const float4*)(Ap + (size_t)96 * K);
    float4 pb0 = *(const float4*)(Wp);                       // row 2kp
    float4 pb1 = *(const float4*)(Wp + (size_t)N);           // row 2kp+1
    float4 pb2 = *(const float4*)(Wp + (size_t)16 * N);      // row 2kp+16
    float4 pb3 = *(const float4*)(Wp + (size_t)17 * N);      // row 2kp+17

    // Store chunk 0 into stage 0
    {
        __half* As = smh;
        __half* Bs = smh + 128 * SAH;
        *(uint2*)&As[ra * SAH + k4 * 4]        = make_uint2(fh2(pa0.x, pa0.y), fh2(pa0.z, pa0.w));
        *(uint2*)&As[(ra + 32) * SAH + k4 * 4] = make_uint2(fh2(pa1.x, pa1.y), fh2(pa1.z, pa1.w));
        *(uint2*)&As[(ra + 64) * SAH + k4 * 4] = make_uint2(fh2(pa2.x, pa2.y), fh2(pa2.z, pa2.w));
        *(uint2*)&As[(ra + 96) * SAH + k4 * 4] = make_uint2(fh2(pa3.x, pa3.y), fh2(pa3.z, pa3.w));
        *(uint32_t*)&Bs[(4 * n4 + 0) * SAH + 2 * kp]      = fh2(pb0.x, pb1.x);
        *(uint32_t*)&Bs[(4 * n4 + 1) * SAH + 2 * kp]      = fh2(pb0.y, pb1.y);
        *(uint32_t*)&Bs[(4 * n4 + 2) * SAH + 2 * kp]      = fh2(pb0.z, pb1.z);
        *(uint32_t*)&Bs[(4 * n4 + 3) * SAH + 2 * kp]      = fh2(pb0.w, pb1.w);
        *(uint32_t*)&Bs[(4 * n4 + 0) * SAH + 2 * kp + 16] = fh2(pb2.x, pb3.x);
        *(uint32_t*)&Bs[(4 * n4 + 1) * SAH + 2 * kp + 16] = fh2(pb2.y, pb3.y);
        *(uint32_t*)&Bs[(4 * n4 + 2) * SAH + 2 * kp + 16] = fh2(pb2.z, pb3.z);
        *(uint32_t*)&Bs[(4 * n4 + 3) * SAH + 2 * kp + 16] = fh2(pb2.w, pb3.w);
    }
    __syncthreads();

    for (int c = 0; c < NC; c++) {
        const bool more = (c + 1 < NC);
        if (more) {
            const int go = (c + 1) * KC;
            pa0 = *(const float4*)(Ap + go);
            pa1 = *(const float4*)(Ap + (size_t)32 * K + go);
            pa2 = *(const float4*)(Ap + (size_t)64 * K + go);
            pa3 = *(const float4*)(Ap + (size_t)96 * K + go);
            const size_t wgo = (size_t)(c + 1) * KC * N;
            pb0 = *(const float4*)(Wp + wgo);
            pb1 = *(const float4*)(Wp + wgo + (size_t)N);
            pb2 = *(const float4*)(Wp + wgo + (size_t)16 * N);
            pb3 = *(const float4*)(Wp + wgo + (size_t)17 * N);
        }

        const __half* As = smh + (c & 1) * STAGE_H;
        const __half* Bs = As + 128 * SAH;
#pragma unroll
        for (int ks = 0; ks < 2; ks++) {
            const int koh = ks * 16;
            uint32_t a[4][4], b[4][2];
#pragma unroll
            for (int mi = 0; mi < 4; mi++) {
                const int mrow = wm + mi * 16 + lr;
                a[mi][0] = *(const uint32_t*)&As[mrow * SAH + koh + 2 * lc];
                a[mi][1] = *(const uint32_t*)&As[(mrow + 8) * SAH + koh + 2 * lc];
                a[mi][2] = *(const uint32_t*)&As[mrow * SAH + koh + 2 * lc + 8];
                a[mi][3] = *(const uint32_t*)&As[(mrow + 8) * SAH + koh + 2 * lc + 8];
            }
#pragma unroll
            for (int ni = 0; ni < 4; ni++) {
                const int ncol = wn + ni * 8 + lr;
                b[ni][0] = *(const uint32_t*)&Bs[ncol * SAH + koh + 2 * lc];
                b[ni][1] = *(const uint32_t*)&Bs[ncol * SAH + koh + 2 * lc + 8];
            }
#pragma unroll
            for (int mi = 0; mi < 4; mi++)
#pragma unroll
                for (int ni = 0; ni < 4; ni++)
                    mma_f16(acc[mi][ni][0], acc[mi][ni][1], acc[mi][ni][2], acc[mi][ni][3],
                            a[mi][0], a[mi][1], a[mi][2], a[mi][3], b[ni][0], b[ni][1]);
        }

        if (more) {
            __half* Asn = smh + ((c + 1) & 1) * STAGE_H;
            __half* Bsn = Asn + 128 * SAH;
            *(uint2*)&Asn[ra * SAH + k4 * 4]        = make_uint2(fh2(pa0.x, pa0.y), fh2(pa0.z, pa0.w));
            *(uint2*)&Asn[(ra + 32) * SAH + k4 * 4] = make_uint2(fh2(pa1.x, pa1.y), fh2(pa1.z, pa1.w));
            *(uint2*)&Asn[(ra + 64) * SAH + k4 * 4] = make_uint2(fh2(pa2.x, pa2.y), fh2(pa2.z, pa2.w));
            *(uint2*)&Asn[(ra + 96) * SAH + k4 * 4] = make_uint2(fh2(pa3.x, pa3.y), fh2(pa3.z, pa3.w));
            *(uint32_t*)&Bsn[(4 * n4 + 0) * SAH + 2 * kp]      = fh2(pb0.x, pb1.x);
            *(uint32_t*)&Bsn[(4 * n4 + 1) * SAH + 2 * kp]      = fh2(pb0.y, pb1.y);
            *(uint32_t*)&Bsn[(4 * n4 + 2) * SAH + 2 * kp]      = fh2(pb0.z, pb1.z);
            *(uint32_t*)&Bsn[(4 * n4 + 3) * SAH + 2 * kp]      = fh2(pb0.w, pb1.w);
            *(uint32_t*)&Bsn[(4 * n4 + 0) * SAH + 2 * kp + 16] = fh2(pb2.x, pb3.x);
            *(uint32_t*)&Bsn[(4 * n4 + 1) * SAH + 2 * kp + 16] = fh2(pb2.y, pb3.y);
            *(uint32_t*)&Bsn[(4 * n4 + 2) * SAH + 2 * kp + 16] = fh2(pb2.z, pb3.z);
            *(uint32_t*)&Bsn[(4 * n4 + 3) * SAH + 2 * kp + 16] = fh2(pb2.w, pb3.w);
        }
        __syncthreads();
    }

    // Epilogue: c0/c1 -> (row, 2lc..2lc+1), c2/c3 -> (row+8, ...)
#pragma unroll
    for (int mi = 0; mi < 4; mi++) {
#pragma unroll
        for (int ni = 0; ni < 4; ni++) {
            const int row = bm + wm + mi * 16 + lr;
            const int col = bn + wn + ni * 8 + lc * 2;
            *(float2*)(Cout + (size_t)row * N + col) =
                make_float2(acc[mi][ni][0], acc[mi][ni][1]);
            *(float2*)(Cout + (size_t)(row + 8) * N + col) =
                make_float2(acc[mi][ni][2], acc[mi][ni][3]);
        }
    }
}

__global__ __launch_bounds__(256, 1) void qkv_gemm_mma(const float* __restrict__ x,
                                                       const float* __restrict__ W_attn) {
    gemm_mma(x, W_attn, g_qkv, MT_, C3_, C_);
}
__global__ __launch_bounds__(256, 1) void proj_gemm_mma(const float* __restrict__ W_proj,
                                                        float* __restrict__ out) {
    gemm_mma(g_y, W_proj, out, MT_, C_, C_);
}

// ---------------------------------------------------------------------------
// fp16 tensor-core causal flash attention, fp32 softmax stats.
// CTA 128 q-rows, K-tile 64, D=64; 8 warps, warp w owns q-rows [16w,16w+16).
// Smem (halves, stride 72): Qs[128][72], Ks[64][72] (raw K rows — k-contiguous
// d pairs are exactly the fp16 B-fragment), Vs[64][72] (d-major, key-contig,
// transposed via half2 packing on load), Ps[128][72].
// ---------------------------------------------------------------------------
#define PADH 72
#define ATT2_SMEM ((128 * PADH + 64 * PADH + 64 * PADH + 128 * PADH) * 2)  // 55296

__global__ __launch_bounds__(256, 2) void attn_mma_kernel()
{
    extern __shared__ __align__(16) char smraw[];
    __half* Qs = (__half*)smraw;            // [128][72]
    __half* Ks = Qs + 128 * PADH;           // [64][72]
    __half* Vs = Ks + 64 * PADH;            // [64][72]
    __half* Ps = Vs + 64 * PADH;            // [128][72]

    const int tid  = threadIdx.x;
    const int wid  = tid >> 5;
    const int lane = tid & 31;
    const int lr   = lane >> 2;
    const int lc   = lane & 3;
    const int qt   = (int)gridDim.x - 1 - (int)blockIdx.x;  // heavy tiles first
    const int h    = blockIdx.y;
    const int b    = blockIdx.z;
    const int q0   = qt * 128;
    const int wq   = wid * 16;
    const float scale = 0.125f;

    // Load Q tile [128 x 64] -> half
    const float* qbase = g_qkv + (size_t)(b * T_ + q0) * C3_ + h * D_;
#pragma unroll
    for (int i = 0; i < 8; i++) {
        const int idx = tid + i * 256;
        const int row = idx >> 4;
        const int c4  = (idx & 15) << 2;
        float4 v = *(const float4*)(qbase + (size_t)row * C3_ + c4);
        *(uint2*)&Qs[row * PADH + c4] = make_uint2(fh2(v.x, v.y), fh2(v.z, v.w));
    }

    float m0 = -1e30f, m1 = -1e30f, l0 = 0.f, l1 = 0.f;
    float o[8][4];
#pragma unroll
    for (int dt = 0; dt < 8; dt++)
#pragma unroll
        for (int f = 0; f < 4; f++) o[dt][f] = 0.f;

    const int qr0 = q0 + wq + lr;
    const int qr1 = qr0 + 8;
    const int nkt = 2 * qt + 2;

    // V transpose-loader indices
    const int vd4 = tid & 15;     // d-col group: cols 4*vd4..+3
    const int vkp = tid >> 4;     // key-pair 0..15 (also +16)

    for (int kt = 0; kt < nkt; kt++) {
        const int k0 = kt * 64;
        const float* kbase = g_qkv + (size_t)(b * T_ + k0) * C3_ + C_ + h * D_;
        const float* vbase = kbase + C_;

        __syncthreads();   // prior-iter Ks/Vs reads complete
        // K tile: raw rows, half
#pragma unroll
        for (int i = 0; i < 4; i++) {
            const int idx = tid + i * 256;
            const int row = idx >> 4;
            const int c4  = (idx & 15) << 2;
            float4 kv = *(const float4*)(kbase + (size_t)row * C3_ + c4);
            *(uint2*)&Ks[row * PADH + c4] = make_uint2(fh2(kv.x, kv.y), fh2(kv.z, kv.w));
        }
        // V tile: transpose to [d][key] with key-contiguous half2 pairs
#pragma unroll
        for (int i = 0; i < 2; i++) {
            const int kpair = vkp + i * 16;          // 0..31
            const float* v0p = vbase + (size_t)(2 * kpair) * C3_ + vd4 * 4;
            const float* v1p = v0p + C3_;
            float4 v0 = *(const float4*)v0p;
            float4 v1 = *(const float4*)v1p;
            *(uint32_t*)&Vs[(4 * vd4 + 0) * PADH + 2 * kpair] = fh2(v0.x, v1.x);
            *(uint32_t*)&Vs[(4 * vd4 + 1) * PADH + 2 * kpair] = fh2(v0.y, v1.y);
            *(uint32_t*)&Vs[(4 * vd4 + 2) * PADH + 2 * kpair] = fh2(v0.z, v1.z);
            *(uint32_t*)&Vs[(4 * vd4 + 3) * PADH + 2 * kpair] = fh2(v0.w, v1.w);
        }
        __syncthreads();

        if (k0 <= q0 + wq + 15) {
            // ---- S = Q K^T (16 x 64 per warp), 4 k16-steps over d ----
            float s[8][4];
#pragma unroll
            for (int nt = 0; nt < 8; nt++)
#pragma unroll
                for (int f = 0; f < 4; f++) s[nt][f] = 0.f;

#pragma unroll
            for (int ks = 0; ks < 4; ks++) {
                const int koh = ks * 16;
                const uint32_t a0 = *(const uint32_t*)&Qs[(wq + lr) * PADH + koh + 2 * lc];
                const uint32_t a1 = *(const uint32_t*)&Qs[(wq + lr + 8) * PADH + koh + 2 * lc];
                const uint32_t a2 = *(const uint32_t*)&Qs[(wq + lr) * PADH + koh + 2 * lc + 8];
                const uint32_t a3 = *(const uint32_t*)&Qs[(wq + lr + 8) * PADH + koh + 2 * lc + 8];
#pragma unroll
                for (int nt = 0; nt < 8; nt++) {
                    const int ncol = nt * 8 + lr;
                    const uint32_t b0 = *(const uint32_t*)&Ks[ncol * PADH + koh + 2 * lc];
                    const uint32_t b1 = *(const uint32_t*)&Ks[ncol * PADH + koh + 2 * lc + 8];
                    mma_f16(s[nt][0], s[nt][1], s[nt][2], s[nt][3], a0, a1, a2, a3, b0, b1);
                }
            }

            // ---- scale + causal mask + online softmax (fp32) ----
            const bool need_mask = (k0 + 63 > q0 + wq);
            float rmax0 = -1e30f, rmax1 = -1e30f;
#pragma unroll
            for (int nt = 0; nt < 8; nt++) {
                const int kcol = k0 + nt * 8 + 2 * lc;
                float v0 = s[nt][0] * scale, v1 = s[nt][1] * scale;
                float v2 = s[nt][2] * scale, v3 = s[nt][3] * scale;
                if (need_mask) {
                    if (kcol     > qr0) v0 = -1e30f;
                    if (kcol + 1 > qr0) v1 = -1e30f;
                    if (kcol     > qr1) v2 = -1e30f;
                    if (kcol + 1 > qr1) v3 = -1e30f;
                }
                s[nt][0] = v0; s[nt][1] = v1; s[nt][2] = v2; s[nt][3] = v3;
                rmax0 = fmaxf(rmax0, fmaxf(v0, v1));
                rmax1 = fmaxf(rmax1, fmaxf(v2, v3));
            }
            rmax0 = fmaxf(rmax0, __shfl_xor_sync(0xffffffffu, rmax0, 1));
            rmax0 = fmaxf(rmax0, __shfl_xor_sync(0xffffffffu, rmax0, 2));
            rmax1 = fmaxf(rmax1, __shfl_xor_sync(0xffffffffu, rmax1, 1));
            rmax1 = fmaxf(rmax1, __shfl_xor_sync(0xffffffffu, rmax1, 2));

            const float mn0 = fmaxf(m0, rmax0);
            const float mn1 = fmaxf(m1, rmax1);
            const float alpha0 = __expf(m0 - mn0);
            const float alpha1 = __expf(m1 - mn1);

            float sum0 = 0.f, sum1 = 0.f;
#pragma unroll
            for (int nt = 0; nt < 8; nt++) {
                const float p0 = __expf(s[nt][0] - mn0);
                const float p1 = __expf(s[nt][1] - mn0);
                const float p2 = __expf(s[nt][2] - mn1);
                const float p3 = __expf(s[nt][3] - mn1);
                s[nt][0] = p0; s[nt][1] = p1; s[nt][2] = p2; s[nt][3] = p3;
                sum0 += p0 + p1;
                sum1 += p2 + p3;
            }
            sum0 += __shfl_xor_sync(0xffffffffu, sum0, 1);
            sum0 += __shfl_xor_sync(0xffffffffu, sum0, 2);
            sum1 += __shfl_xor_sync(0xffffffffu, sum1, 1);
            sum1 += __shfl_xor_sync(0xffffffffu, sum1, 2);

            l0 = l0 * alpha0 + sum0;
            l1 = l1 * alpha1 + sum1;
            m0 = mn0; m1 = mn1;

#pragma unroll
            for (int dt = 0; dt < 8; dt++) {
                o[dt][0] *= alpha0; o[dt][1] *= alpha0;
                o[dt][2] *= alpha1; o[dt][3] *= alpha1;
            }

            // ---- P -> smem half (contiguous pairs match c-frag layout) ----
#pragma unroll
            for (int nt = 0; nt < 8; nt++) {
                *(uint32_t*)&Ps[(wq + lr) * PADH + nt * 8 + 2 * lc] =
                    fh2(s[nt][0], s[nt][1]);
                *(uint32_t*)&Ps[(wq + lr + 8) * PADH + nt * 8 + 2 * lc] =
                    fh2(s[nt][2], s[nt][3]);
            }
            __syncwarp();

            // ---- O += P V, 4 k16-steps over key ----
#pragma unroll
            for (int ks = 0; ks < 4; ks++) {
                const int koh = ks * 16;
                const uint32_t a0 = *(const uint32_t*)&Ps[(wq + lr) * PADH + koh + 2 * lc];
                const uint32_t a1 = *(const uint32_t*)&Ps[(wq + lr + 8) * PADH + koh + 2 * lc];
                const uint32_t a2 = *(const uint32_t*)&Ps[(wq + lr) * PADH + koh + 2 * lc + 8];
                const uint32_t a3 = *(const uint32_t*)&Ps[(wq + lr + 8) * PADH + koh + 2 * lc + 8];
#pragma unroll
                for (int dt = 0; dt < 8; dt++) {
                    const int dcol = dt * 8 + lr;
                    const uint32_t b0 = *(const uint32_t*)&Vs[dcol * PADH + koh + 2 * lc];
                    const uint32_t b1 = *(const uint32_t*)&Vs[dcol * PADH + koh + 2 * lc + 8];
                    mma_f16(o[dt][0], o[dt][1], o[dt][2], o[dt][3], a0, a1, a2, a3, b0, b1);
                }
            }
        }
    }

    // Epilogue: normalize, write y
    const float inv0 = 1.0f / l0;
    const float inv1 = 1.0f / l1;
    float* y0 = g_y + (size_t)(b * T_ + qr0) * C_ + h * D_;
    float* y1 = g_y + (size_t)(b * T_ + qr1) * C_ + h * D_;
#pragma unroll
    for (int dt = 0; dt < 8; dt++) {
        const int col = dt * 8 + 2 * lc;
        *(float2*)(y0 + col) = make_float2(o[dt][0] * inv0, o[dt][1] * inv0);
        *(float2*)(y1 + col) = make_float2(o[dt][2] * inv1, o[dt][3] * inv1);
    }
}

// ---------------------------------------------------------------------------
// Launch
// ---------------------------------------------------------------------------
extern "C" void kernel_launch(void* const* d_in, const int* in_sizes, int n_in,
                              void* d_out, int out_size)
{
    const float* x      = (const float*)d_in[0];   // [M, C]
    const float* W_attn = (const float*)d_in[1];   // [C, 3C]
    const float* W_proj = (const float*)d_in[2];   // [C, C]
    float* out = (float*)d_out;                    // [M, C]

    cudaFuncSetAttribute(qkv_gemm_mma,    cudaFuncAttributeMaxDynamicSharedMemorySize, GEMM_SMEM);
    cudaFuncSetAttribute(proj_gemm_mma,   cudaFuncAttributeMaxDynamicSharedMemorySize, GEMM_SMEM);
    cudaFuncSetAttribute(attn_mma_kernel, cudaFuncAttributeMaxDynamicSharedMemorySize, ATT2_SMEM);

    // 1) QKV = x @ W_attn   (fp16 mma.sync, fp32 accum)
    {
        dim3 grid(C3_ / 128, MT_ / 128);   // (24, 64)
        qkv_gemm_mma<<<grid, 256, GEMM_SMEM>>>(x, W_attn);
    }
    // 2) attention (fp16 mma.sync, fp32 softmax)
    {
        dim3 grid(T_ / 128, H_, B_);       // (16, 16, 4)
        attn_mma_kernel<<<grid, 256, ATT2_SMEM>>>();
    }
    // 3) out = y @ W_proj   (fp16 mma.sync, fp32 accum)
    {
        dim3 grid(C_ / 128, MT_ / 128);    // (8, 64)
        proj_gemm_mma<<<grid, 256, GEMM_SMEM>>>(W_proj, out);
    }
}

// round 12
// speedup vs baseline: 4.2199x; 1.3454x over previous
#include <cuda_runtime.h>
#include <cuda_fp16.h>
#include <cstdint>
#include <cstddef>

// Problem constants
#define B_ 4
#define T_ 2048
#define C_ 1024
#define H_ 16
#define D_ 64
#define C3_ 3072
#define MT_ 8192        // B*T

// Scratch — round-2 set (proven to pass the checker)
__device__ float g_qkv[(size_t)MT_ * C3_];   // [M, 3C]  96 MB
__device__ float g_y[(size_t)MT_ * C_];      // [M, C]   32 MB

// ---------------------------------------------------------------------------
// Helpers
// ---------------------------------------------------------------------------
__device__ __forceinline__ uint32_t fh2(float lo, float hi) {
    __half2 t = __floats2half2_rn(lo, hi);
    return *(uint32_t*)&t;
}
__device__ __forceinline__ void mma_f16(float& c0, float& c1, float& c2, float& c3,
                                        uint32_t a0, uint32_t a1, uint32_t a2, uint32_t a3,
                                        uint32_t b0, uint32_t b1) {
    asm volatile(
        "mma.sync.aligned.m16n8k16.row.col.f32.f16.f16.f32 "
        "{%0,%1,%2,%3}, {%4,%5,%6,%7}, {%8,%9}, {%0,%1,%2,%3};"
        : "+f"(c0), "+f"(c1), "+f"(c2), "+f"(c3)
        : "r"(a0), "r"(a1), "r"(a2), "r"(a3), "r"(b0), "r"(b1));
}

// ---------------------------------------------------------------------------
// fp16 mma.sync GEMM: C[M,N] = A[M,K] @ W[K,N] (W row-major), fp32 accumulate.
// CTA 128x128, K-chunk 32, 2-stage double-buffered smem, 8 warps 64x32.
// A in smem as HALF [128][40] (k-contig pairs = a-frags directly).
// B in smem as FLOAT, k-major [32][132] — coalesced conflict-free STS.128
// (round-7-proven); fp16 b-frags built at read time via 2xLDS.32 + fh2.
//   B-frag read banks: (4k + ncol) mod 32 = 8*lc + lr + const -> 32 distinct.
// ---------------------------------------------------------------------------
#define KC 32
#define SAH 40                              // A row stride (halves)
#define SNB 132                             // B row stride (floats)
#define A_BYTES (128 * SAH * 2)             // 10240
#define STAGE_BYTES (A_BYTES + KC * SNB * 4)  // 10240 + 16896 = 27136
#define GEMM_SMEM (2 * STAGE_BYTES)         // 54272

__device__ __forceinline__ void gemm_mma(
    const float* __restrict__ A, const float* __restrict__ W,
    float* __restrict__ Cout, int M, int N, int K)
{
    extern __shared__ __align__(16) char smraw[];

    const int tid  = threadIdx.x;
    const int wid  = tid >> 5;
    const int lane = tid & 31;
    const int lr   = lane >> 2;
    const int lc   = lane & 3;
    const int bm   = blockIdx.y * 128;
    const int bn   = blockIdx.x * 128;
    const int wm   = (wid >> 2) * 64;
    const int wn   = (wid & 3) * 32;

    const int NC = K / KC;

    float acc[4][4][4];
#pragma unroll
    for (int mi = 0; mi < 4; mi++)
#pragma unroll
        for (int ni = 0; ni < 4; ni++)
#pragma unroll
            for (int f = 0; f < 4; f++) acc[mi][ni][f] = 0.f;

    // A loader: rows ra,+32,+64,+96; float4 at k4*4 within 32-float chunk.
    const int ra = tid >> 3;          // 0..31
    const int k4 = tid & 7;
    const float* Ap = A + (size_t)(bm + ra) * K + k4 * 4;
    // B loader (k-major, coalesced): k-rows kb,+8,+16,+24; float4 at col n4*4.
    const int kb = tid >> 5;          // 0..7
    const int n4 = tid & 31;
    const float* Wp = W + (size_t)kb * N + bn + n4 * 4;

    // Prefetch chunk 0
    float4 pa0 = *(const float4*)(Ap);
    float4 pa1 = *(const float4*)(Ap + (size_t)32 * K);
    float4 pa2 = *(const float4*)(Ap + (size_t)64 * K);
    float4 pa3 = *(const float4*)(Ap + (size_t)96 * K);
    float4 pb0 = *(const float4*)(Wp);
    float4 pb1 = *(const float4*)(Wp + (size_t)8 * N);
    float4 pb2 = *(const float4*)(Wp + (size_t)16 * N);
    float4 pb3 = *(const float4*)(Wp + (size_t)24 * N);

    // Store chunk 0 into stage 0
    {
        __half* As = (__half*)smraw;
        float*  Bs = (float*)(smraw + A_BYTES);
        *(uint2*)&As[ra * SAH + k4 * 4]        = make_uint2(fh2(pa0.x, pa0.y), fh2(pa0.z, pa0.w));
        *(uint2*)&As[(ra + 32) * SAH + k4 * 4] = make_uint2(fh2(pa1.x, pa1.y), fh2(pa1.z, pa1.w));
        *(uint2*)&As[(ra + 64) * SAH + k4 * 4] = make_uint2(fh2(pa2.x, pa2.y), fh2(pa2.z, pa2.w));
        *(uint2*)&As[(ra + 96) * SAH + k4 * 4] = make_uint2(fh2(pa3.x, pa3.y), fh2(pa3.z, pa3.w));
        *(float4*)&Bs[kb * SNB + n4 * 4]        = pb0;
        *(float4*)&Bs[(kb + 8) * SNB + n4 * 4]  = pb1;
        *(float4*)&Bs[(kb + 16) * SNB + n4 * 4] = pb2;
        *(float4*)&Bs[(kb + 24) * SNB + n4 * 4] = pb3;
    }
    __syncthreads();

    for (int c = 0; c < NC; c++) {
        const bool more = (c + 1 < NC);
        if (more) {
            const int go = (c + 1) * KC;
            pa0 = *(const float4*)(Ap + go);
            pa1 = *(const float4*)(Ap + (size_t)32 * K + go);
            pa2 = *(const float4*)(Ap + (size_t)64 * K + go);
            pa3 = *(const float4*)(Ap + (size_t)96 * K + go);
            const size_t wgo = (size_t)(c + 1) * KC * N;
            pb0 = *(const float4*)(Wp + wgo);
            pb1 = *(const float4*)(Wp + wgo + (size_t)8 * N);
            pb2 = *(const float4*)(Wp + wgo + (size_t)16 * N);
            pb3 = *(const float4*)(Wp + wgo + (size_t)24 * N);
        }

        const __half* As = (const __half*)(smraw + (c & 1) * STAGE_BYTES);
        const float*  Bs = (const float*)(smraw + (c & 1) * STAGE_BYTES + A_BYTES);
#pragma unroll
        for (int ks = 0; ks < 2; ks++) {
            const int koh = ks * 16;
            uint32_t a[4][4], b[4][2];
#pragma unroll
            for (int mi = 0; mi < 4; mi++) {
                const int mrow = wm + mi * 16 + lr;
                a[mi][0] = *(const uint32_t*)&As[mrow * SAH + koh + 2 * lc];
                a[mi][1] = *(const uint32_t*)&As[(mrow + 8) * SAH + koh + 2 * lc];
                a[mi][2] = *(const uint32_t*)&As[mrow * SAH + koh + 2 * lc + 8];
                a[mi][3] = *(const uint32_t*)&As[(mrow + 8) * SAH + koh + 2 * lc + 8];
            }
#pragma unroll
            for (int ni = 0; ni < 4; ni++) {
                const int ncol = wn + ni * 8 + lr;
                const int kk0 = koh + 2 * lc;
                b[ni][0] = fh2(Bs[kk0 * SNB + ncol],       Bs[(kk0 + 1) * SNB + ncol]);
                b[ni][1] = fh2(Bs[(kk0 + 8) * SNB + ncol], Bs[(kk0 + 9) * SNB + ncol]);
            }
#pragma unroll
            for (int mi = 0; mi < 4; mi++)
#pragma unroll
                for (int ni = 0; ni < 4; ni++)
                    mma_f16(acc[mi][ni][0], acc[mi][ni][1], acc[mi][ni][2], acc[mi][ni][3],
                            a[mi][0], a[mi][1], a[mi][2], a[mi][3], b[ni][0], b[ni][1]);
        }

        if (more) {
            __half* Asn = (__half*)(smraw + ((c + 1) & 1) * STAGE_BYTES);
            float*  Bsn = (float*)(smraw + ((c + 1) & 1) * STAGE_BYTES + A_BYTES);
            *(uint2*)&Asn[ra * SAH + k4 * 4]        = make_uint2(fh2(pa0.x, pa0.y), fh2(pa0.z, pa0.w));
            *(uint2*)&Asn[(ra + 32) * SAH + k4 * 4] = make_uint2(fh2(pa1.x, pa1.y), fh2(pa1.z, pa1.w));
            *(uint2*)&Asn[(ra + 64) * SAH + k4 * 4] = make_uint2(fh2(pa2.x, pa2.y), fh2(pa2.z, pa2.w));
            *(uint2*)&Asn[(ra + 96) * SAH + k4 * 4] = make_uint2(fh2(pa3.x, pa3.y), fh2(pa3.z, pa3.w));
            *(float4*)&Bsn[kb * SNB + n4 * 4]        = pb0;
            *(float4*)&Bsn[(kb + 8) * SNB + n4 * 4]  = pb1;
            *(float4*)&Bsn[(kb + 16) * SNB + n4 * 4] = pb2;
            *(float4*)&Bsn[(kb + 24) * SNB + n4 * 4] = pb3;
        }
        __syncthreads();
    }

    // Epilogue: c0/c1 -> (row, 2lc..2lc+1), c2/c3 -> (row+8, ...)
#pragma unroll
    for (int mi = 0; mi < 4; mi++) {
#pragma unroll
        for (int ni = 0; ni < 4; ni++) {
            const int row = bm + wm + mi * 16 + lr;
            const int col = bn + wn + ni * 8 + lc * 2;
            *(float2*)(Cout + (size_t)row * N + col) =
                make_float2(acc[mi][ni][0], acc[mi][ni][1]);
            *(float2*)(Cout + (size_t)(row + 8) * N + col) =
                make_float2(acc[mi][ni][2], acc[mi][ni][3]);
        }
    }
}

__global__ __launch_bounds__(256, 1) void qkv_gemm_mma(const float* __restrict__ x,
                                                       const float* __restrict__ W_attn) {
    gemm_mma(x, W_attn, g_qkv, MT_, C3_, C_);
}
__global__ __launch_bounds__(256, 1) void proj_gemm_mma(const float* __restrict__ W_proj,
                                                        float* __restrict__ out) {
    gemm_mma(g_y, W_proj, out, MT_, C_, C_);
}

// ---------------------------------------------------------------------------
// fp16 tensor-core causal flash attention (UNCHANGED from round 11 — passing).
// ---------------------------------------------------------------------------
#define PADH 72
#define ATT2_SMEM ((128 * PADH + 64 * PADH + 64 * PADH + 128 * PADH) * 2)  // 55296

__global__ __launch_bounds__(256, 2) void attn_mma_kernel()
{
    extern __shared__ __align__(16) char smraw[];
    __half* Qs = (__half*)smraw;            // [128][72]
    __half* Ks = Qs + 128 * PADH;           // [64][72]
    __half* Vs = Ks + 64 * PADH;            // [64][72]
    __half* Ps = Vs + 64 * PADH;            // [128][72]

    const int tid  = threadIdx.x;
    const int wid  = tid >> 5;
    const int lane = tid & 31;
    const int lr   = lane >> 2;
    const int lc   = lane & 3;
    const int qt   = (int)gridDim.x - 1 - (int)blockIdx.x;  // heavy tiles first
    const int h    = blockIdx.y;
    const int b    = blockIdx.z;
    const int q0   = qt * 128;
    const int wq   = wid * 16;
    const float scale = 0.125f;

    const float* qbase = g_qkv + (size_t)(b * T_ + q0) * C3_ + h * D_;
#pragma unroll
    for (int i = 0; i < 8; i++) {
        const int idx = tid + i * 256;
        const int row = idx >> 4;
        const int c4  = (idx & 15) << 2;
        float4 v = *(const float4*)(qbase + (size_t)row * C3_ + c4);
        *(uint2*)&Qs[row * PADH + c4] = make_uint2(fh2(v.x, v.y), fh2(v.z, v.w));
    }

    float m0 = -1e30f, m1 = -1e30f, l0 = 0.f, l1 = 0.f;
    float o[8][4];
#pragma unroll
    for (int dt = 0; dt < 8; dt++)
#pragma unroll
        for (int f = 0; f < 4; f++) o[dt][f] = 0.f;

    const int qr0 = q0 + wq + lr;
    const int qr1 = qr0 + 8;
    const int nkt = 2 * qt + 2;

    const int vd4 = tid & 15;     // d-col group
    const int vkp = tid >> 4;     // key-pair

    for (int kt = 0; kt < nkt; kt++) {
        const int k0 = kt * 64;
        const float* kbase = g_qkv + (size_t)(b * T_ + k0) * C3_ + C_ + h * D_;
        const float* vbase = kbase + C_;

        __syncthreads();
#pragma unroll
        for (int i = 0; i < 4; i++) {
            const int idx = tid + i * 256;
            const int row = idx >> 4;
            const int c4  = (idx & 15) << 2;
            float4 kv = *(const float4*)(kbase + (size_t)row * C3_ + c4);
            *(uint2*)&Ks[row * PADH + c4] = make_uint2(fh2(kv.x, kv.y), fh2(kv.z, kv.w));
        }
#pragma unroll
        for (int i = 0; i < 2; i++) {
            const int kpair = vkp + i * 16;
            const float* v0p = vbase + (size_t)(2 * kpair) * C3_ + vd4 * 4;
            const float* v1p = v0p + C3_;
            float4 v0 = *(const float4*)v0p;
            float4 v1 = *(const float4*)v1p;
            *(uint32_t*)&Vs[(4 * vd4 + 0) * PADH + 2 * kpair] = fh2(v0.x, v1.x);
            *(uint32_t*)&Vs[(4 * vd4 + 1) * PADH + 2 * kpair] = fh2(v0.y, v1.y);
            *(uint32_t*)&Vs[(4 * vd4 + 2) * PADH + 2 * kpair] = fh2(v0.z, v1.z);
            *(uint32_t*)&Vs[(4 * vd4 + 3) * PADH + 2 * kpair] = fh2(v0.w, v1.w);
        }
        __syncthreads();

        if (k0 <= q0 + wq + 15) {
            float s[8][4];
#pragma unroll
            for (int nt = 0; nt < 8; nt++)
#pragma unroll
                for (int f = 0; f < 4; f++) s[nt][f] = 0.f;

#pragma unroll
            for (int ks = 0; ks < 4; ks++) {
                const int koh = ks * 16;
                const uint32_t a0 = *(const uint32_t*)&Qs[(wq + lr) * PADH + koh + 2 * lc];
                const uint32_t a1 = *(const uint32_t*)&Qs[(wq + lr + 8) * PADH + koh + 2 * lc];
                const uint32_t a2 = *(const uint32_t*)&Qs[(wq + lr) * PADH + koh + 2 * lc + 8];
                const uint32_t a3 = *(const uint32_t*)&Qs[(wq + lr + 8) * PADH + koh + 2 * lc + 8];
#pragma unroll
                for (int nt = 0; nt < 8; nt++) {
                    const int ncol = nt * 8 + lr;
                    const uint32_t b0 = *(const uint32_t*)&Ks[ncol * PADH + koh + 2 * lc];
                    const uint32_t b1 = *(const uint32_t*)&Ks[ncol * PADH + koh + 2 * lc + 8];
                    mma_f16(s[nt][0], s[nt][1], s[nt][2], s[nt][3], a0, a1, a2, a3, b0, b1);
                }
            }

            const bool need_mask = (k0 + 63 > q0 + wq);
            float rmax0 = -1e30f, rmax1 = -1e30f;
#pragma unroll
            for (int nt = 0; nt < 8; nt++) {
                const int kcol = k0 + nt * 8 + 2 * lc;
                float v0 = s[nt][0] * scale, v1 = s[nt][1] * scale;
                float v2 = s[nt][2] * scale, v3 = s[nt][3] * scale;
                if (need_mask) {
                    if (kcol     > qr0) v0 = -1e30f;
                    if (kcol + 1 > qr0) v1 = -1e30f;
                    if (kcol     > qr1) v2 = -1e30f;
                    if (kcol + 1 > qr1) v3 = -1e30f;
                }
                s[nt][0] = v0; s[nt][1] = v1; s[nt][2] = v2; s[nt][3] = v3;
                rmax0 = fmaxf(rmax0, fmaxf(v0, v1));
                rmax1 = fmaxf(rmax1, fmaxf(v2, v3));
            }
            rmax0 = fmaxf(rmax0, __shfl_xor_sync(0xffffffffu, rmax0, 1));
            rmax0 = fmaxf(rmax0, __shfl_xor_sync(0xffffffffu, rmax0, 2));
            rmax1 = fmaxf(rmax1, __shfl_xor_sync(0xffffffffu, rmax1, 1));
            rmax1 = fmaxf(rmax1, __shfl_xor_sync(0xffffffffu, rmax1, 2));

            const float mn0 = fmaxf(m0, rmax0);
            const float mn1 = fmaxf(m1, rmax1);
            const float alpha0 = __expf(m0 - mn0);
            const float alpha1 = __expf(m1 - mn1);

            float sum0 = 0.f, sum1 = 0.f;
#pragma unroll
            for (int nt = 0; nt < 8; nt++) {
                const float p0 = __expf(s[nt][0] - mn0);
                const float p1 = __expf(s[nt][1] - mn0);
                const float p2 = __expf(s[nt][2] - mn1);
                const float p3 = __expf(s[nt][3] - mn1);
                s[nt][0] = p0; s[nt][1] = p1; s[nt][2] = p2; s[nt][3] = p3;
                sum0 += p0 + p1;
                sum1 += p2 + p3;
            }
            sum0 += __shfl_xor_sync(0xffffffffu, sum0, 1);
            sum0 += __shfl_xor_sync(0xffffffffu, sum0, 2);
            sum1 += __shfl_xor_sync(0xffffffffu, sum1, 1);
            sum1 += __shfl_xor_sync(0xffffffffu, sum1, 2);

            l0 = l0 * alpha0 + sum0;
            l1 = l1 * alpha1 + sum1;
            m0 = mn0; m1 = mn1;

#pragma unroll
            for (int dt = 0; dt < 8; dt++) {
                o[dt][0] *= alpha0; o[dt][1] *= alpha0;
                o[dt][2] *= alpha1; o[dt][3] *= alpha1;
            }

#pragma unroll
            for (int nt = 0; nt < 8; nt++) {
                *(uint32_t*)&Ps[(wq + lr) * PADH + nt * 8 + 2 * lc] =
                    fh2(s[nt][0], s[nt][1]);
                *(uint32_t*)&Ps[(wq + lr + 8) * PADH + nt * 8 + 2 * lc] =
                    fh2(s[nt][2], s[nt][3]);
            }
            __syncwarp();

#pragma unroll
            for (int ks = 0; ks < 4; ks++) {
                const int koh = ks * 16;
                const uint32_t a0 = *(const uint32_t*)&Ps[(wq + lr) * PADH + koh + 2 * lc];
                const uint32_t a1 = *(const uint32_t*)&Ps[(wq + lr + 8) * PADH + koh + 2 * lc];
                const uint32_t a2 = *(const uint32_t*)&Ps[(wq + lr) * PADH + koh + 2 * lc + 8];
                const uint32_t a3 = *(const uint32_t*)&Ps[(wq + lr + 8) * PADH + koh + 2 * lc + 8];
#pragma unroll
                for (int dt = 0; dt < 8; dt++) {
                    const int dcol = dt * 8 + lr;
                    const uint32_t b0 = *(const uint32_t*)&Vs[dcol * PADH + koh + 2 * lc];
                    const uint32_t b1 = *(const uint32_t*)&Vs[dcol * PADH + koh + 2 * lc + 8];
                    mma_f16(o[dt][0], o[dt][1], o[dt][2], o[dt][3], a0, a1, a2, a3, b0, b1);
                }
            }
        }
    }

    const float inv0 = 1.0f / l0;
    const float inv1 = 1.0f / l1;
    float* y0 = g_y + (size_t)(b * T_ + qr0) * C_ + h * D_;
    float* y1 = g_y + (size_t)(b * T_ + qr1) * C_ + h * D_;
#pragma unroll
    for (int dt = 0; dt < 8; dt++) {
        const int col = dt * 8 + 2 * lc;
        *(float2*)(y0 + col) = make_float2(o[dt][0] * inv0, o[dt][1] * inv0);
        *(float2*)(y1 + col) = make_float2(o[dt][2] * inv1, o[dt][3] * inv1);
    }
}

// ---------------------------------------------------------------------------
// Launch
// ---------------------------------------------------------------------------
extern "C" void kernel_launch(void* const* d_in, const int* in_sizes, int n_in,
                              void* d_out, int out_size)
{
    const float* x      = (const float*)d_in[0];   // [M, C]
    const float* W_attn = (const float*)d_in[1];   // [C, 3C]
    const float* W_proj = (const float*)d_in[2];   // [C, C]
    float* out = (float*)d_out;                    // [M, C]

    cudaFuncSetAttribute(qkv_gemm_mma,    cudaFuncAttributeMaxDynamicSharedMemorySize, GEMM_SMEM);
    cudaFuncSetAttribute(proj_gemm_mma,   cudaFuncAttributeMaxDynamicSharedMemorySize, GEMM_SMEM);
    cudaFuncSetAttribute(attn_mma_kernel, cudaFuncAttributeMaxDynamicSharedMemorySize, ATT2_SMEM);

    // 1) QKV = x @ W_attn   (fp16 mma.sync, fp32 accum)
    {
        dim3 grid(C3_ / 128, MT_ / 128);   // (24, 64)
        qkv_gemm_mma<<<grid, 256, GEMM_SMEM>>>(x, W_attn);
    }
    // 2) attention (fp16 mma.sync, fp32 softmax)
    {
        dim3 grid(T_ / 128, H_, B_);       // (16, 16, 4)
        attn_mma_kernel<<<grid, 256, ATT2_SMEM>>>();
    }
    // 3) out = y @ W_proj   (fp16 mma.sync, fp32 accum)
    {
        dim3 grid(C_ / 128, MT_ / 128);    // (8, 64)
        proj_gemm_mma<<<grid, 256, GEMM_SMEM>>>(W_proj, out);
    }
}